// round 14
// baseline (speedup 1.0000x reference)
#include <cuda_runtime.h>
#include <cuda_fp16.h>
#include <math_constants.h>
#include <cstdint>

#define BB 4
#define TT 2048
#define DM 1024
#define NH 16
#define DH 64

// Scratch (plain fp16 row-major; ldmatrix handles fragment distribution)
__device__ __half g_qkv2[(size_t)BB * TT * 3 * DM]; // q(rope*scale*log2e), k(rope), v
__device__ __half g_att [(size_t)BB * TT * DM];     // attention out
__device__ __half g_x16 [(size_t)BB * TT * DM];     // x fp16
__device__ __half g_wq  [(size_t)3 * DM * DM];      // qkv_w fp16
__device__ __half g_wp  [(size_t)DM * DM];          // proj_w fp16

// ===========================================================================
// Helpers
// ===========================================================================
__device__ __forceinline__ uint32_t packh2(float x, float y) {
    __half2 h = __floats2half2_rn(x, y);
    return *reinterpret_cast<uint32_t*>(&h);
}

// pack two fp32 (log2-domain) into half2 and take exp2 -> fp16 pair
__device__ __forceinline__ uint32_t pexp2(float x, float y) {
    __half2 h = h2exp2(__floats2half2_rn(x, y));
    return *reinterpret_cast<uint32_t*>(&h);
}

// D += A(16x16,row) * B(16x8,col), fp16 inputs, fp32 accum
__device__ __forceinline__ void mma16(float* c, const uint32_t* a,
                                      uint32_t b0, uint32_t b1) {
    asm volatile(
        "mma.sync.aligned.m16n8k16.row.col.f32.f16.f16.f32 "
        "{%0,%1,%2,%3}, {%4,%5,%6,%7}, {%8,%9}, {%0,%1,%2,%3};"
        : "+f"(c[0]), "+f"(c[1]), "+f"(c[2]), "+f"(c[3])
        : "r"(a[0]), "r"(a[1]), "r"(a[2]), "r"(a[3]), "r"(b0), "r"(b1));
}

__device__ __forceinline__ void ldm_x4(uint32_t* r, uint32_t addr) {
    asm volatile("ldmatrix.sync.aligned.m8n8.x4.shared.b16 {%0,%1,%2,%3}, [%4];"
                 : "=r"(r[0]), "=r"(r[1]), "=r"(r[2]), "=r"(r[3]) : "r"(addr));
}

__device__ __forceinline__ void ldm_x4_t(uint32_t* r, uint32_t addr) {
    asm volatile("ldmatrix.sync.aligned.m8n8.x4.trans.shared.b16 {%0,%1,%2,%3}, [%4];"
                 : "=r"(r[0]), "=r"(r[1]), "=r"(r[2]), "=r"(r[3]) : "r"(addr));
}

__device__ __forceinline__ uint32_t smem_u32(const void* p) {
    uint32_t a;
    asm("{ .reg .u64 t; cvta.to.shared.u64 t, %1; cvt.u32.u64 %0, t; }"
        : "=r"(a) : "l"(p));
    return a;
}
__device__ __forceinline__ void cpa16(uint32_t s, const void* g) {
    asm volatile("cp.async.ca.shared.global [%0], [%1], 16;" :: "r"(s), "l"(g));
}
#define CPA_COMMIT() asm volatile("cp.async.commit_group;" ::: "memory")
#define CPA_WAIT(n)  asm volatile("cp.async.wait_group %0;" :: "n"(n) : "memory")

// ===========================================================================
// prep_plain: fp32 -> fp16, 8 consecutive elements per thread
// ===========================================================================
__global__ void prep_plain(const float* __restrict__ src, __half* __restrict__ dst,
                           int n8) {
    int i = blockIdx.x * blockDim.x + threadIdx.x;
    if (i >= n8) return;
    const float4* s = (const float4*)src + (size_t)i * 2;
    float4 f0 = s[0], f1 = s[1];
    uint4 o;
    o.x = packh2(f0.x, f0.y); o.y = packh2(f0.z, f0.w);
    o.z = packh2(f1.x, f1.y); o.w = packh2(f1.z, f1.w);
    *((uint4*)(dst + (size_t)i * 8)) = o;
}

// ===========================================================================
// GEMM: C = A @ W^T + bias (fp16 in, fp32 accum). CTA 128x128, 8 warps (4m x 2n),
// warp tile 32x64, BK=64 halves. 128B rows, chunk swizzle c^(r&7),
// 3-stage cp.async, fragments via ldmatrix.x4, 2 CTAs/SM -> 16 warps/SM.
// mode 0: fp32 out. mode 1: fused qkv rope/scale epilogue (fp16 out;
//         q scaled by 0.125*log2(e) for log2-domain softmax).
// ===========================================================================
#define GTILEB 16384                        // bytes per operand tile (128 x 128B)
#define GSMEM_TOTAL (3 * 2 * GTILEB)        // 98304 B

__global__ void __launch_bounds__(256, 2)
gemm_tc(const __half* __restrict__ A, const __half* __restrict__ W,
        const float* __restrict__ bias, void* __restrict__ Cv,
        int M, int N, int K, int mode,
        const float* __restrict__ fcos, const float* __restrict__ fsin) {
    extern __shared__ uint32_t gsm[];
    const int tid  = threadIdx.x;
    const int wid  = tid >> 5;
    const int lane = tid & 31;
    const int g    = lane >> 2;
    const int tig  = lane & 3;
    const int wm   = wid & 3;       // 4 m-groups of 32 rows
    const int wn   = wid >> 2;      // 2 n-groups of 64 cols

    const int m0 = blockIdx.y * 128;
    const int n0 = blockIdx.x * 128;
    const uint32_t sbase = smem_u32(gsm);

    // ldmatrix lane-address offsets (bytes within a tile), loop-invariant
    const int l8  = lane & 7;
    const int lA8 = ((lane >> 3) & 1) * 8;
    const int lhi = lane >> 4;
    const int bhi = (lane >> 3) & 1;
    const int bA8 = lhi * 8;
    uint32_t aOff[2][4], bOff[4][4];
    #pragma unroll
    for (int i = 0; i < 2; i++) {
        int r = wm * 32 + i * 16 + l8 + lA8;
        #pragma unroll
        for (int s = 0; s < 4; s++)
            aOff[i][s] = r * 128 + (((2 * s + lhi) ^ (r & 7)) << 4);
    }
    #pragma unroll
    for (int p = 0; p < 4; p++) {
        int r = wn * 64 + 16 * p + l8 + bA8;
        #pragma unroll
        for (int s = 0; s < 4; s++)
            bOff[p][s] = r * 128 + (((2 * s + bhi) ^ (r & 7)) << 4);
    }

    float acc[2][8][4];
    #pragma unroll
    for (int i = 0; i < 2; i++)
        #pragma unroll
        for (int j = 0; j < 8; j++)
            #pragma unroll
            for (int e = 0; e < 4; e++) acc[i][j][e] = 0.f;

    const int NK = K >> 6;   // K/64

    auto load_stage = [&](int st, int k0) {
        #pragma unroll
        for (int it = 0; it < 8; it++) {
            int lin   = tid + it * 256;      // 0..2047
            int which = lin >> 10;           // 0=A, 1=B
            int r     = (lin & 1023) >> 3;   // 0..127
            int c4    = lin & 7;             // 16B chunk
            const __half* src = which
                ? W + (size_t)(n0 + r) * K + k0 + c4 * 8
                : A + (size_t)(m0 + r) * K + k0 + c4 * 8;
            cpa16(sbase + (st * 2 + which) * GTILEB + r * 128
                        + ((c4 ^ (r & 7)) << 4), src);
        }
    };

    load_stage(0, 0);
    CPA_COMMIT();
    load_stage(1, 64);
    CPA_COMMIT();

    int cur = 0, pre = 2;
    for (int kt = 0; kt < NK; kt++) {
        if (kt + 1 < NK) CPA_WAIT(1); else CPA_WAIT(0);
        __syncthreads();

        if (kt + 2 < NK) {
            load_stage(pre, (kt + 2) << 6);
            CPA_COMMIT();
        }

        const uint32_t aBase = sbase + cur * 2 * GTILEB;
        const uint32_t bBase = aBase + GTILEB;

        #pragma unroll
        for (int s = 0; s < 4; s++) {
            uint32_t a[2][4], bf[4][4];
            #pragma unroll
            for (int i = 0; i < 2; i++) ldm_x4(a[i], aBase + aOff[i][s]);
            #pragma unroll
            for (int p = 0; p < 4; p++) ldm_x4(bf[p], bBase + bOff[p][s]);
            #pragma unroll
            for (int j = 0; j < 8; j++) {
                uint32_t b0 = bf[j >> 1][(j & 1) * 2];
                uint32_t b1 = bf[j >> 1][(j & 1) * 2 + 1];
                #pragma unroll
                for (int i = 0; i < 2; i++) mma16(acc[i][j], a[i], b0, b1);
            }
        }

        cur = (cur == 2) ? 0 : cur + 1;
        pre = (pre == 2) ? 0 : pre + 1;
    }

    #pragma unroll
    for (int i = 0; i < 2; i++) {
        int row0 = m0 + wm * 32 + i * 16 + g;
        int row1 = row0 + 8;
        #pragma unroll
        for (int j = 0; j < 8; j++) {
            int col = n0 + wn * 64 + j * 8 + 2 * tig;
            float bv0 = bias[col], bv1 = bias[col + 1];
            float v00 = acc[i][j][0] + bv0, v01 = acc[i][j][1] + bv1;
            float v10 = acc[i][j][2] + bv0, v11 = acc[i][j][3] + bv1;
            if (mode == 0) {
                float* C = (float*)Cv;
                *(float2*)(C + (size_t)row0 * N + col) = make_float2(v00, v01);
                *(float2*)(C + (size_t)row1 * N + col) = make_float2(v10, v11);
            } else {
                __half* C = (__half*)Cv;
                int sec = col >> 10;           // 0 q, 1 k, 2 v
                int d   = col & 63;
                if (sec < 2) {
                    // q gets 1/sqrt(dh) * log2(e) so softmax runs in exp2 domain
                    float sc = (sec == 0) ? 0.18033688011112042f : 1.f;
                    int t0i = row0 & (TT - 1), t1i = row1 & (TT - 1);
                    float c0 = fcos[t0i * 32 + (d >> 1)], s0 = fsin[t0i * 32 + (d >> 1)];
                    float c1 = fcos[t1i * 32 + (d >> 1)], s1 = fsin[t1i * 32 + (d >> 1)];
                    *(__half2*)(C + (size_t)row0 * N + col) =
                        __floats2half2_rn((v00 * c0 - v01 * s0) * sc,
                                          (v00 * s0 + v01 * c0) * sc);
                    *(__half2*)(C + (size_t)row1 * N + col) =
                        __floats2half2_rn((v10 * c1 - v11 * s1) * sc,
                                          (v10 * s1 + v11 * c1) * sc);
                } else {
                    *(__half2*)(C + (size_t)row0 * N + col) = __floats2half2_rn(v00, v01);
                    *(__half2*)(C + (size_t)row1 * N + col) = __floats2half2_rn(v10, v11);
                }
            }
        }
    }
}

// ===========================================================================
// Flash attention v13: 128-q blocks, 128 threads (4 warps x 32 rows),
// 2 CTAs/SM. 128-key staging (two 64-key halves per barrier), double-buffered.
// V via ldmatrix.trans straight from qkv2. log2 softmax, fp16x2 exp2,
// ones-MMA row sums.
// ===========================================================================
#define QB 16384                           // Q tile bytes (128 x 128B)
#define KHB 16384                          // K bytes per 128-key stage
#define STB 32768                          // stage bytes (K+V)
#define ASMEM_TOTAL (QB + 2 * STB)         // 81920 B
#define ONESH2 0x3C003C00u                 // half2(1.0, 1.0)

__global__ void __launch_bounds__(128, 2)
attn_tc(const __half* __restrict__ qkv2, __half* __restrict__ att_out) {
    extern __shared__ uint32_t asmw[];
    const uint32_t sbase = smem_u32(asmw);

    const int tid  = threadIdx.x;
    const int w    = tid >> 5;
    const int lane = tid & 31;
    const int g    = lane >> 2;
    const int tig  = lane & 3;
    const int rb   = w * 32;

    const int b   = blockIdx.y >> 4;
    const int hh  = blockIdx.y & 15;
    const int bxx = gridDim.x - 1 - blockIdx.x;   // longest blocks first
    const int q0  = bxx * 128;

    const __half* qb = qkv2 + (size_t)b * TT * (3 * DM) + hh * 64;
    const __half* kb = qb + DM;

    // ldmatrix lane offsets
    const int l8  = lane & 7;
    const int lA8 = ((lane >> 3) & 1) * 8;   // A-form / trans-form row offset
    const int lhi = lane >> 4;               // A-form / trans-form chunk offset
    const int bhi = (lane >> 3) & 1;         // B-form chunk offset
    const int bA8 = lhi * 8;                 // B-form row offset
    uint32_t kOff[4][4], vOff[4][4];
    #pragma unroll
    for (int p = 0; p < 4; p++) {
        int r = 16 * p + l8 + bA8;
        #pragma unroll
        for (int s = 0; s < 4; s++)
            kOff[p][s] = r * 128 + (((2 * s + bhi) ^ (r & 7)) << 4);
    }
    // V (trans form): rows = 16s + l8 + lA8, chunk = 2e + lhi
    #pragma unroll
    for (int e = 0; e < 4; e++) {
        #pragma unroll
        for (int s = 0; s < 4; s++) {
            int r = 16 * s + l8 + lA8;
            vOff[e][s] = r * 128 + (((2 * e + lhi) ^ (r & 7)) << 4);
        }
    }

    // --- stage Q: 128 rows x 8 chunks ---
    #pragma unroll
    for (int it = 0; it < 8; it++) {
        int lin = tid + it * 128;            // 0..1023
        int r = lin >> 3, c4 = lin & 7;
        cpa16(sbase + r * 128 + ((c4 ^ (r & 7)) << 4),
              qb + (size_t)(q0 + r) * (3 * DM) + c4 * 8);
    }
    CPA_COMMIT();

    // stage 128 keys of K and V (256 rows x 8 chunks = 16/thread)
    auto stage_kv = [&](int buf, int j0) {
        #pragma unroll
        for (int it = 0; it < 16; it++) {
            int lin   = tid + it * 128;      // 0..2047
            int which = lin >> 10;           // 0 K, 1 V
            int r  = (lin & 1023) >> 3;      // 0..127
            int c4 = lin & 7;
            const __half* src = kb + (size_t)(j0 + r) * (3 * DM)
                              + (which ? DM : 0) + c4 * 8;
            cpa16(sbase + QB + buf * STB + which * KHB + r * 128
                        + ((c4 ^ (r & 7)) << 4), src);
        }
    };

    stage_kv(0, 0);
    CPA_COMMIT();
    CPA_WAIT(1);          // Q done
    __syncthreads();

    // --- Q fragments (once) ---
    uint32_t qa[2][4][4];
    #pragma unroll
    for (int i = 0; i < 2; i++) {
        int r = rb + i * 16 + l8 + lA8;
        #pragma unroll
        for (int s = 0; s < 4; s++)
            ldm_x4(qa[i][s], sbase + r * 128 + (((2 * s + lhi) ^ (r & 7)) << 4));
    }

    float o[2][8][4];
    #pragma unroll
    for (int i = 0; i < 2; i++)
        #pragma unroll
        for (int j = 0; j < 8; j++)
            #pragma unroll
            for (int e = 0; e < 4; e++) o[i][j][e] = 0.f;
    float lf[2][4] = {{0.f, 0.f, 0.f, 0.f}, {0.f, 0.f, 0.f, 0.f}};
    float mv[2][2] = {{-CUDART_INF_F, -CUDART_INF_F}, {-CUDART_INF_F, -CUDART_INF_F}};

    const int ntiles = bxx + 1;   // 128-key tiles

    for (int tile = 0; tile < ntiles; tile++) {
        const int cur = tile & 1;

        if (tile + 1 < ntiles) {
            stage_kv(cur ^ 1, (tile + 1) * 128);
            CPA_COMMIT();
            CPA_WAIT(1);
        } else {
            CPA_WAIT(0);
        }
        __syncthreads();

        #pragma unroll
        for (int half = 0; half < 2; half++) {
            const int j0 = tile * 128 + half * 64;
            const uint32_t kBase = sbase + QB + cur * STB + half * 8192;
            const uint32_t vBase = kBase + KHB;
            const bool active = (j0 <= q0 + rb + 31);
            if (!active) continue;

            // --- S = Q @ K^T  (log2 domain) ---
            float p[2][8][4];
            #pragma unroll
            for (int i = 0; i < 2; i++)
                #pragma unroll
                for (int j = 0; j < 8; j++)
                    #pragma unroll
                    for (int e = 0; e < 4; e++) p[i][j][e] = 0.f;
            #pragma unroll
            for (int s = 0; s < 4; s++) {
                uint32_t bf[4][4];
                #pragma unroll
                for (int pp = 0; pp < 4; pp++) ldm_x4(bf[pp], kBase + kOff[pp][s]);
                #pragma unroll
                for (int j = 0; j < 8; j++) {
                    uint32_t b0 = bf[j >> 1][(j & 1) * 2];
                    uint32_t b1 = bf[j >> 1][(j & 1) * 2 + 1];
                    mma16(p[0][j], qa[0][s], b0, b1);
                    mma16(p[1][j], qa[1][s], b0, b1);
                }
            }

            // --- causal mask on diagonal warp-tiles ---
            if (j0 + 63 > q0 + rb) {
                #pragma unroll
                for (int i = 0; i < 2; i++) {
                    int row0 = q0 + rb + i * 16 + g;
                    int row1 = row0 + 8;
                    #pragma unroll
                    for (int j = 0; j < 8; j++) {
                        int col = j0 + j * 8 + 2 * tig;
                        if (col > row0)     p[i][j][0] = -CUDART_INF_F;
                        if (col + 1 > row0) p[i][j][1] = -CUDART_INF_F;
                        if (col > row1)     p[i][j][2] = -CUDART_INF_F;
                        if (col + 1 > row1) p[i][j][3] = -CUDART_INF_F;
                    }
                }
            }

            // --- online max update + rescale ---
            #pragma unroll
            for (int i = 0; i < 2; i++) {
                float r0 = -CUDART_INF_F, r1 = -CUDART_INF_F;
                #pragma unroll
                for (int j = 0; j < 8; j++) {
                    r0 = fmaxf(r0, fmaxf(p[i][j][0], p[i][j][1]));
                    r1 = fmaxf(r1, fmaxf(p[i][j][2], p[i][j][3]));
                }
                r0 = fmaxf(r0, __shfl_xor_sync(0xffffffffu, r0, 1));
                r0 = fmaxf(r0, __shfl_xor_sync(0xffffffffu, r0, 2));
                r1 = fmaxf(r1, __shfl_xor_sync(0xffffffffu, r1, 1));
                r1 = fmaxf(r1, __shfl_xor_sync(0xffffffffu, r1, 2));
                float nm0 = fmaxf(mv[i][0], r0);
                float nm1 = fmaxf(mv[i][1], r1);
                float sc0 = exp2f(mv[i][0] - nm0);
                float sc1 = exp2f(mv[i][1] - nm1);
                mv[i][0] = nm0; mv[i][1] = nm1;
                lf[i][0] *= sc0; lf[i][2] *= sc1;
                #pragma unroll
                for (int j = 0; j < 8; j++) {
                    o[i][j][0] *= sc0; o[i][j][1] *= sc0;
                    o[i][j][2] *= sc1; o[i][j][3] *= sc1;
                }
            }

            // --- P = exp2(S - m) as fp16 A-frags; l += P@1; O += P@V ---
            #pragma unroll
            for (int s = 0; s < 4; s++) {
                uint32_t pa[2][4];
                #pragma unroll
                for (int i = 0; i < 2; i++) {
                    float nm0 = mv[i][0], nm1 = mv[i][1];
                    pa[i][0] = pexp2(p[i][2 * s][0] - nm0,     p[i][2 * s][1] - nm0);
                    pa[i][1] = pexp2(p[i][2 * s][2] - nm1,     p[i][2 * s][3] - nm1);
                    pa[i][2] = pexp2(p[i][2 * s + 1][0] - nm0, p[i][2 * s + 1][1] - nm0);
                    pa[i][3] = pexp2(p[i][2 * s + 1][2] - nm1, p[i][2 * s + 1][3] - nm1);
                }
                mma16(lf[0], pa[0], ONESH2, ONESH2);   // row sums
                mma16(lf[1], pa[1], ONESH2, ONESH2);

                uint32_t vf[4][4];
                #pragma unroll
                for (int e = 0; e < 4; e++) ldm_x4_t(vf[e], vBase + vOff[e][s]);
                #pragma unroll
                for (int dj = 0; dj < 8; dj++) {
                    uint32_t b0 = vf[dj >> 1][(dj & 1) * 2];
                    uint32_t b1 = vf[dj >> 1][(dj & 1) * 2 + 1];
                    mma16(o[0][dj], pa[0], b0, b1);
                    mma16(o[1][dj], pa[1], b0, b1);
                }
            }
        }
        __syncthreads();
    }

    // --- normalize + store fp16 ---
    #pragma unroll
    for (int i = 0; i < 2; i++) {
        float inv0 = 1.f / lf[i][0], inv1 = 1.f / lf[i][2];
        int row0 = q0 + rb + i * 16 + g;
        __half* op0 = att_out + ((size_t)(b * TT + row0)) * DM + hh * 64;
        __half* op1 = op0 + (size_t)8 * DM;
        #pragma unroll
        for (int dj = 0; dj < 8; dj++) {
            int col = dj * 8 + 2 * tig;
            *(__half2*)(op0 + col) = __floats2half2_rn(o[i][dj][0] * inv0,
                                                       o[i][dj][1] * inv0);
            *(__half2*)(op1 + col) = __floats2half2_rn(o[i][dj][2] * inv1,
                                                       o[i][dj][3] * inv1);
        }
    }
}

// ---------------------------------------------------------------------------
// kernel_launch
// Inputs: 0:x  1:mask(unused)  2:freqs_cos  3:freqs_sin
//         4:qkv_w  5:qkv_b  6:proj_w  7:proj_b
// ---------------------------------------------------------------------------
extern "C" void kernel_launch(void* const* d_in, const int* in_sizes, int n_in,
                              void* d_out, int out_size) {
    const float* x      = (const float*)d_in[0];
    const float* fcos   = (const float*)d_in[2];
    const float* fsin   = (const float*)d_in[3];
    const float* qkv_w  = (const float*)d_in[4];
    const float* qkv_b  = (const float*)d_in[5];
    const float* proj_w = (const float*)d_in[6];
    const float* proj_b = (const float*)d_in[7];
    float* out = (float*)d_out;

    __half *qkv2, *att, *x16, *wq, *wp;
    cudaGetSymbolAddress((void**)&qkv2, g_qkv2);
    cudaGetSymbolAddress((void**)&att,  g_att);
    cudaGetSymbolAddress((void**)&x16,  g_x16);
    cudaGetSymbolAddress((void**)&wq,   g_wq);
    cudaGetSymbolAddress((void**)&wp,   g_wp);

    cudaFuncSetAttribute(gemm_tc, cudaFuncAttributeMaxDynamicSharedMemorySize,
                         GSMEM_TOTAL);
    cudaFuncSetAttribute(attn_tc, cudaFuncAttributeMaxDynamicSharedMemorySize,
                         ASMEM_TOTAL);

    const int M = BB * TT;   // 8192

    // 0) operand prep: fp32 -> fp16
    prep_plain<<<(M * DM / 8) / 256, 256>>>(x, x16, M * DM / 8);
    prep_plain<<<(3 * DM * DM / 8) / 256, 256>>>(qkv_w, wq, 3 * DM * DM / 8);
    prep_plain<<<(DM * DM / 8) / 256, 256>>>(proj_w, wp, DM * DM / 8);

    // 1) QKV GEMM with fused rope epilogue -> qkv2 (fp16)
    {
        dim3 grid(3 * DM / 128, M / 128);
        gemm_tc<<<grid, 256, GSMEM_TOTAL>>>(x16, wq, qkv_b, qkv2, M, 3 * DM, DM,
                                            1, fcos, fsin);
    }
    // 2) causal attention -> att (fp16), V via ldmatrix.trans
    {
        dim3 grid(TT / 128, BB * NH);
        attn_tc<<<grid, 128, ASMEM_TOTAL>>>(qkv2, att);
    }
    // 3) output projection -> d_out (fp32)
    {
        dim3 grid(DM / 128, M / 128);
        gemm_tc<<<grid, 256, GSMEM_TOTAL>>>(att, wp, proj_b, out, M, DM, DM,
                                            0, nullptr, nullptr);
    }
}

// round 15
// speedup vs baseline: 1.1408x; 1.1408x over previous
#include <cuda_runtime.h>
#include <cuda.h>
#include <cuda_fp16.h>
#include <math_constants.h>
#include <cstdint>

#define BB 4
#define TT 2048
#define DM 1024
#define NH 16
#define DH 64

// Scratch (plain fp16 row-major; ldmatrix handles fragment distribution)
__device__ __half g_qkv2[(size_t)BB * TT * 3 * DM]; // q(rope*scale*log2e), k(rope), v
__device__ __half g_att [(size_t)BB * TT * DM];     // attention out
__device__ __half g_x16 [(size_t)BB * TT * DM];     // x fp16
__device__ __half g_wq  [(size_t)3 * DM * DM];      // qkv_w fp16
__device__ __half g_wp  [(size_t)DM * DM];          // proj_w fp16

// ===========================================================================
// Helpers
// ===========================================================================
__device__ __forceinline__ uint32_t packh2(float x, float y) {
    __half2 h = __floats2half2_rn(x, y);
    return *reinterpret_cast<uint32_t*>(&h);
}

__device__ __forceinline__ uint32_t pexp2(float x, float y) {
    __half2 h = h2exp2(__floats2half2_rn(x, y));
    return *reinterpret_cast<uint32_t*>(&h);
}

// D += A(16x16,row) * B(16x8,col), fp16 inputs, fp32 accum
__device__ __forceinline__ void mma16(float* c, const uint32_t* a,
                                      uint32_t b0, uint32_t b1) {
    asm volatile(
        "mma.sync.aligned.m16n8k16.row.col.f32.f16.f16.f32 "
        "{%0,%1,%2,%3}, {%4,%5,%6,%7}, {%8,%9}, {%0,%1,%2,%3};"
        : "+f"(c[0]), "+f"(c[1]), "+f"(c[2]), "+f"(c[3])
        : "r"(a[0]), "r"(a[1]), "r"(a[2]), "r"(a[3]), "r"(b0), "r"(b1));
}

__device__ __forceinline__ void ldm_x4(uint32_t* r, uint32_t addr) {
    asm volatile("ldmatrix.sync.aligned.m8n8.x4.shared.b16 {%0,%1,%2,%3}, [%4];"
                 : "=r"(r[0]), "=r"(r[1]), "=r"(r[2]), "=r"(r[3]) : "r"(addr));
}

__device__ __forceinline__ void ldm_x4_t(uint32_t* r, uint32_t addr) {
    asm volatile("ldmatrix.sync.aligned.m8n8.x4.trans.shared.b16 {%0,%1,%2,%3}, [%4];"
                 : "=r"(r[0]), "=r"(r[1]), "=r"(r[2]), "=r"(r[3]) : "r"(addr));
}

__device__ __forceinline__ uint32_t smem_u32(const void* p) {
    uint32_t a;
    asm("{ .reg .u64 t; cvta.to.shared.u64 t, %1; cvt.u32.u64 %0, t; }"
        : "=r"(a) : "l"(p));
    return a;
}
__device__ __forceinline__ void cpa16(uint32_t s, const void* g) {
    asm volatile("cp.async.ca.shared.global [%0], [%1], 16;" :: "r"(s), "l"(g));
}
#define CPA_COMMIT() asm volatile("cp.async.commit_group;" ::: "memory")
#define CPA_WAIT(n)  asm volatile("cp.async.wait_group %0;" :: "n"(n) : "memory")

// --- TMA / mbarrier ---
__device__ __forceinline__ void tma2d(uint32_t dst, const CUtensorMap* tm,
                                      int cx, int cy, uint32_t mb) {
    asm volatile(
        "cp.async.bulk.tensor.2d.shared::cta.global.tile.mbarrier::complete_tx::bytes "
        "[%0], [%1, {%2, %3}], [%4];"
        :: "r"(dst), "l"(tm), "r"(cx), "r"(cy), "r"(mb) : "memory");
}
__device__ __forceinline__ void mbar_init(uint32_t mb, uint32_t cnt) {
    asm volatile("mbarrier.init.shared.b64 [%0], %1;" :: "r"(mb), "r"(cnt) : "memory");
}
__device__ __forceinline__ void mbar_expect(uint32_t mb, uint32_t bytes) {
    asm volatile("mbarrier.arrive.expect_tx.shared.b64 _, [%0], %1;"
                 :: "r"(mb), "r"(bytes) : "memory");
}
__device__ __forceinline__ void mbar_wait(uint32_t mb, uint32_t parity) {
    asm volatile(
        "{\n\t.reg .pred P;\n\t"
        "WAIT_%=:\n\t"
        "mbarrier.try_wait.parity.shared::cta.b64 P, [%0], %1, 0x989680;\n\t"
        "@P bra.uni DONE_%=;\n\t"
        "bra.uni WAIT_%=;\n\t"
        "DONE_%=:\n\t}"
        :: "r"(mb), "r"(parity) : "memory");
}

// ===========================================================================
// prep_plain: fp32 -> fp16, 8 consecutive elements per thread
// ===========================================================================
__global__ void prep_plain(const float* __restrict__ src, __half* __restrict__ dst,
                           int n8) {
    int i = blockIdx.x * blockDim.x + threadIdx.x;
    if (i >= n8) return;
    const float4* s = (const float4*)src + (size_t)i * 2;
    float4 f0 = s[0], f1 = s[1];
    uint4 o;
    o.x = packh2(f0.x, f0.y); o.y = packh2(f0.z, f0.w);
    o.z = packh2(f1.x, f1.y); o.w = packh2(f1.z, f1.w);
    *((uint4*)(dst + (size_t)i * 8)) = o;
}

// ===========================================================================
// GEMM v14: C = A @ W^T + bias. Tiles staged by TMA (SW128 == c^(r&7) layout),
// 3-stage mbarrier pipeline. CTA 128x128, 8 warps (4m x 2n), warp 32x64,
// fragments via ldmatrix.x4, 2 CTAs/SM.
// mode 0: fp32 out. mode 1: fused qkv rope/scale epilogue (fp16 out).
// ===========================================================================
#define GTILEB 16384                            // bytes per operand tile
#define GSMEM_TOTAL (6 * GTILEB + 1024 + 64)    // tiles + align slack + mbars

__global__ void __launch_bounds__(256, 2)
gemm_tc(const __grid_constant__ CUtensorMap tmA,
        const __grid_constant__ CUtensorMap tmB,
        const float* __restrict__ bias, void* __restrict__ Cv,
        int M, int N, int K, int mode,
        const float* __restrict__ fcos, const float* __restrict__ fsin) {
    extern __shared__ uint32_t gsm[];
    const uint32_t ab   = (smem_u32(gsm) + 1023u) & ~1023u;   // 1KB-aligned tiles
    const uint32_t mbar = ab + 6 * GTILEB;                     // 3 mbarriers

    const int tid  = threadIdx.x;
    const int wid  = tid >> 5;
    const int lane = tid & 31;
    const int g    = lane >> 2;
    const int tig  = lane & 3;
    const int wm   = wid & 3;
    const int wn   = wid >> 2;

    const int m0 = blockIdx.y * 128;
    const int n0 = blockIdx.x * 128;

    // ldmatrix lane-address offsets (bytes within a tile)
    const int l8  = lane & 7;
    const int lA8 = ((lane >> 3) & 1) * 8;
    const int lhi = lane >> 4;
    const int bhi = (lane >> 3) & 1;
    const int bA8 = lhi * 8;
    uint32_t aOff[2][4], bOff[4][4];
    #pragma unroll
    for (int i = 0; i < 2; i++) {
        int r = wm * 32 + i * 16 + l8 + lA8;
        #pragma unroll
        for (int s = 0; s < 4; s++)
            aOff[i][s] = r * 128 + (((2 * s + lhi) ^ (r & 7)) << 4);
    }
    #pragma unroll
    for (int p = 0; p < 4; p++) {
        int r = wn * 64 + 16 * p + l8 + bA8;
        #pragma unroll
        for (int s = 0; s < 4; s++)
            bOff[p][s] = r * 128 + (((2 * s + bhi) ^ (r & 7)) << 4);
    }

    if (tid == 0) {
        mbar_init(mbar, 1);
        mbar_init(mbar + 8, 1);
        mbar_init(mbar + 16, 1);
    }
    __syncthreads();

    float acc[2][8][4];
    #pragma unroll
    for (int i = 0; i < 2; i++)
        #pragma unroll
        for (int j = 0; j < 8; j++)
            #pragma unroll
            for (int e = 0; e < 4; e++) acc[i][j][e] = 0.f;

    const int NK = K >> 6;   // K/64

    auto load_stage = [&](int st, int k0) {
        if (tid == 0) {
            uint32_t mb = mbar + st * 8;
            mbar_expect(mb, 2 * GTILEB);
            tma2d(ab + st * 2 * GTILEB,          &tmA, k0, m0, mb);
            tma2d(ab + st * 2 * GTILEB + GTILEB, &tmB, k0, n0, mb);
        }
    };

    load_stage(0, 0);
    load_stage(1, 64);

    int ph0 = 0, ph1 = 0, ph2 = 0;
    int cur = 0, pre = 2;
    for (int kt = 0; kt < NK; kt++) {
        if (cur == 0)      { mbar_wait(mbar,      ph0); ph0 ^= 1; }
        else if (cur == 1) { mbar_wait(mbar + 8,  ph1); ph1 ^= 1; }
        else               { mbar_wait(mbar + 16, ph2); ph2 ^= 1; }
        __syncthreads();   // all warps done with stage 'pre' (read at kt-1)

        if (kt + 2 < NK) load_stage(pre, (kt + 2) << 6);

        const uint32_t aBase = ab + cur * 2 * GTILEB;
        const uint32_t bBase = aBase + GTILEB;

        #pragma unroll
        for (int s = 0; s < 4; s++) {
            uint32_t a[2][4], bf[4][4];
            #pragma unroll
            for (int i = 0; i < 2; i++) ldm_x4(a[i], aBase + aOff[i][s]);
            #pragma unroll
            for (int p = 0; p < 4; p++) ldm_x4(bf[p], bBase + bOff[p][s]);
            #pragma unroll
            for (int j = 0; j < 8; j++) {
                uint32_t b0 = bf[j >> 1][(j & 1) * 2];
                uint32_t b1 = bf[j >> 1][(j & 1) * 2 + 1];
                #pragma unroll
                for (int i = 0; i < 2; i++) mma16(acc[i][j], a[i], b0, b1);
            }
        }

        cur = (cur == 2) ? 0 : cur + 1;
        pre = (pre == 2) ? 0 : pre + 1;
    }

    #pragma unroll
    for (int i = 0; i < 2; i++) {
        int row0 = m0 + wm * 32 + i * 16 + g;
        int row1 = row0 + 8;
        #pragma unroll
        for (int j = 0; j < 8; j++) {
            int col = n0 + wn * 64 + j * 8 + 2 * tig;
            float bv0 = bias[col], bv1 = bias[col + 1];
            float v00 = acc[i][j][0] + bv0, v01 = acc[i][j][1] + bv1;
            float v10 = acc[i][j][2] + bv0, v11 = acc[i][j][3] + bv1;
            if (mode == 0) {
                float* C = (float*)Cv;
                *(float2*)(C + (size_t)row0 * N + col) = make_float2(v00, v01);
                *(float2*)(C + (size_t)row1 * N + col) = make_float2(v10, v11);
            } else {
                __half* C = (__half*)Cv;
                int sec = col >> 10;           // 0 q, 1 k, 2 v
                int d   = col & 63;
                if (sec < 2) {
                    // q gets 1/sqrt(dh) * log2(e) for log2-domain softmax
                    float sc = (sec == 0) ? 0.18033688011112042f : 1.f;
                    int t0i = row0 & (TT - 1), t1i = row1 & (TT - 1);
                    float c0 = fcos[t0i * 32 + (d >> 1)], s0 = fsin[t0i * 32 + (d >> 1)];
                    float c1 = fcos[t1i * 32 + (d >> 1)], s1 = fsin[t1i * 32 + (d >> 1)];
                    *(__half2*)(C + (size_t)row0 * N + col) =
                        __floats2half2_rn((v00 * c0 - v01 * s0) * sc,
                                          (v00 * s0 + v01 * c0) * sc);
                    *(__half2*)(C + (size_t)row1 * N + col) =
                        __floats2half2_rn((v10 * c1 - v11 * s1) * sc,
                                          (v10 * s1 + v11 * c1) * sc);
                } else {
                    *(__half2*)(C + (size_t)row0 * N + col) = __floats2half2_rn(v00, v01);
                    *(__half2*)(C + (size_t)row1 * N + col) = __floats2half2_rn(v10, v11);
                }
            }
        }
    }
}

// ===========================================================================
// Flash attention (best config, R13=378.8us): 128-q blocks, 128 threads
// (4 warps x 32 rows), 2 CTAs/SM, 64-key double-buffered cp.async staging,
// V via ldmatrix.trans, log2 softmax, fp16x2 exp2, ones-MMA row sums.
// ===========================================================================
#define QB 16384                           // Q tile bytes (128 x 128B)
#define KVB 8192                           // K or V tile bytes (64 x 128B)
#define ASMEM_TOTAL (QB + 4 * KVB)         // 49152 B
#define ONESH2 0x3C003C00u                 // half2(1.0, 1.0)

__global__ void __launch_bounds__(128, 2)
attn_tc(const __half* __restrict__ qkv2, __half* __restrict__ att_out) {
    extern __shared__ uint32_t asmw[];
    const uint32_t sbase = smem_u32(asmw);

    const int tid  = threadIdx.x;
    const int w    = tid >> 5;
    const int lane = tid & 31;
    const int g    = lane >> 2;
    const int tig  = lane & 3;
    const int rb   = w * 32;

    const int b   = blockIdx.y >> 4;
    const int hh  = blockIdx.y & 15;
    const int bxx = gridDim.x - 1 - blockIdx.x;   // longest blocks first
    const int q0  = bxx * 128;

    const __half* qb = qkv2 + (size_t)b * TT * (3 * DM) + hh * 64;
    const __half* kb = qb + DM;

    // ldmatrix lane offsets
    const int l8  = lane & 7;
    const int lA8 = ((lane >> 3) & 1) * 8;
    const int lhi = lane >> 4;
    const int bhi = (lane >> 3) & 1;
    const int bA8 = lhi * 8;
    uint32_t kOff[4][4], vOff[4][4];
    #pragma unroll
    for (int p = 0; p < 4; p++) {
        int r = 16 * p + l8 + bA8;
        #pragma unroll
        for (int s = 0; s < 4; s++)
            kOff[p][s] = r * 128 + (((2 * s + bhi) ^ (r & 7)) << 4);
    }
    #pragma unroll
    for (int e = 0; e < 4; e++) {
        #pragma unroll
        for (int s = 0; s < 4; s++) {
            int r = 16 * s + l8 + lA8;
            vOff[e][s] = r * 128 + (((2 * e + lhi) ^ (r & 7)) << 4);
        }
    }

    // --- stage Q ---
    #pragma unroll
    for (int it = 0; it < 8; it++) {
        int lin = tid + it * 128;
        int r = lin >> 3, c4 = lin & 7;
        cpa16(sbase + r * 128 + ((c4 ^ (r & 7)) << 4),
              qb + (size_t)(q0 + r) * (3 * DM) + c4 * 8);
    }
    CPA_COMMIT();

    auto stage_kv = [&](int buf, int j0) {
        #pragma unroll
        for (int it = 0; it < 8; it++) {
            int lin   = tid + it * 128;
            int which = lin >> 9;            // 0 K, 1 V
            int r  = (lin & 511) >> 3;
            int c4 = lin & 7;
            const __half* src = kb + (size_t)(j0 + r) * (3 * DM)
                              + (which ? DM : 0) + c4 * 8;
            cpa16(sbase + QB + (which * 2 + buf) * KVB + r * 128
                        + ((c4 ^ (r & 7)) << 4), src);
        }
    };

    stage_kv(0, 0);
    CPA_COMMIT();
    CPA_WAIT(1);
    __syncthreads();

    // --- Q fragments (once) ---
    uint32_t qa[2][4][4];
    #pragma unroll
    for (int i = 0; i < 2; i++) {
        int r = rb + i * 16 + l8 + lA8;
        #pragma unroll
        for (int s = 0; s < 4; s++)
            ldm_x4(qa[i][s], sbase + r * 128 + (((2 * s + lhi) ^ (r & 7)) << 4));
    }

    float o[2][8][4];
    #pragma unroll
    for (int i = 0; i < 2; i++)
        #pragma unroll
        for (int j = 0; j < 8; j++)
            #pragma unroll
            for (int e = 0; e < 4; e++) o[i][j][e] = 0.f;
    float lf[2][4] = {{0.f, 0.f, 0.f, 0.f}, {0.f, 0.f, 0.f, 0.f}};
    float mv[2][2] = {{-CUDART_INF_F, -CUDART_INF_F}, {-CUDART_INF_F, -CUDART_INF_F}};

    const int ntiles = 2 * (bxx + 1);

    for (int tile = 0; tile < ntiles; tile++) {
        const int j0  = tile * 64;
        const int cur = tile & 1;

        if (tile + 1 < ntiles) {
            stage_kv(cur ^ 1, j0 + 64);
            CPA_COMMIT();
            CPA_WAIT(1);
        } else {
            CPA_WAIT(0);
        }
        __syncthreads();

        const uint32_t kBase = sbase + QB + cur * KVB;
        const uint32_t vBase = sbase + QB + (2 + cur) * KVB;
        const bool active = (j0 <= q0 + rb + 31);

        if (active) {
            // --- S = Q @ K^T (log2 domain) ---
            float p[2][8][4];
            #pragma unroll
            for (int i = 0; i < 2; i++)
                #pragma unroll
                for (int j = 0; j < 8; j++)
                    #pragma unroll
                    for (int e = 0; e < 4; e++) p[i][j][e] = 0.f;
            #pragma unroll
            for (int s = 0; s < 4; s++) {
                uint32_t bf[4][4];
                #pragma unroll
                for (int pp = 0; pp < 4; pp++) ldm_x4(bf[pp], kBase + kOff[pp][s]);
                #pragma unroll
                for (int j = 0; j < 8; j++) {
                    uint32_t b0 = bf[j >> 1][(j & 1) * 2];
                    uint32_t b1 = bf[j >> 1][(j & 1) * 2 + 1];
                    mma16(p[0][j], qa[0][s], b0, b1);
                    mma16(p[1][j], qa[1][s], b0, b1);
                }
            }

            // --- causal mask on diagonal tiles ---
            if (j0 + 63 > q0 + rb) {
                #pragma unroll
                for (int i = 0; i < 2; i++) {
                    int row0 = q0 + rb + i * 16 + g;
                    int row1 = row0 + 8;
                    #pragma unroll
                    for (int j = 0; j < 8; j++) {
                        int col = j0 + j * 8 + 2 * tig;
                        if (col > row0)     p[i][j][0] = -CUDART_INF_F;
                        if (col + 1 > row0) p[i][j][1] = -CUDART_INF_F;
                        if (col > row1)     p[i][j][2] = -CUDART_INF_F;
                        if (col + 1 > row1) p[i][j][3] = -CUDART_INF_F;
                    }
                }
            }

            // --- online max update + rescale ---
            #pragma unroll
            for (int i = 0; i < 2; i++) {
                float r0 = -CUDART_INF_F, r1 = -CUDART_INF_F;
                #pragma unroll
                for (int j = 0; j < 8; j++) {
                    r0 = fmaxf(r0, fmaxf(p[i][j][0], p[i][j][1]));
                    r1 = fmaxf(r1, fmaxf(p[i][j][2], p[i][j][3]));
                }
                r0 = fmaxf(r0, __shfl_xor_sync(0xffffffffu, r0, 1));
                r0 = fmaxf(r0, __shfl_xor_sync(0xffffffffu, r0, 2));
                r1 = fmaxf(r1, __shfl_xor_sync(0xffffffffu, r1, 1));
                r1 = fmaxf(r1, __shfl_xor_sync(0xffffffffu, r1, 2));
                float nm0 = fmaxf(mv[i][0], r0);
                float nm1 = fmaxf(mv[i][1], r1);
                float sc0 = exp2f(mv[i][0] - nm0);
                float sc1 = exp2f(mv[i][1] - nm1);
                mv[i][0] = nm0; mv[i][1] = nm1;
                lf[i][0] *= sc0; lf[i][2] *= sc1;
                #pragma unroll
                for (int j = 0; j < 8; j++) {
                    o[i][j][0] *= sc0; o[i][j][1] *= sc0;
                    o[i][j][2] *= sc1; o[i][j][3] *= sc1;
                }
            }

            // --- P = exp2(S - m) as fp16 A-frags; l += P@1; O += P@V ---
            #pragma unroll
            for (int s = 0; s < 4; s++) {
                uint32_t pa[2][4];
                #pragma unroll
                for (int i = 0; i < 2; i++) {
                    float nm0 = mv[i][0], nm1 = mv[i][1];
                    pa[i][0] = pexp2(p[i][2 * s][0] - nm0,     p[i][2 * s][1] - nm0);
                    pa[i][1] = pexp2(p[i][2 * s][2] - nm1,     p[i][2 * s][3] - nm1);
                    pa[i][2] = pexp2(p[i][2 * s + 1][0] - nm0, p[i][2 * s + 1][1] - nm0);
                    pa[i][3] = pexp2(p[i][2 * s + 1][2] - nm1, p[i][2 * s + 1][3] - nm1);
                }
                mma16(lf[0], pa[0], ONESH2, ONESH2);   // row sums
                mma16(lf[1], pa[1], ONESH2, ONESH2);

                uint32_t vf[4][4];
                #pragma unroll
                for (int e = 0; e < 4; e++) ldm_x4_t(vf[e], vBase + vOff[e][s]);
                #pragma unroll
                for (int dj = 0; dj < 8; dj++) {
                    uint32_t b0 = vf[dj >> 1][(dj & 1) * 2];
                    uint32_t b1 = vf[dj >> 1][(dj & 1) * 2 + 1];
                    mma16(o[0][dj], pa[0], b0, b1);
                    mma16(o[1][dj], pa[1], b0, b1);
                }
            }
        }
        __syncthreads();
    }

    // --- normalize + store fp16 ---
    #pragma unroll
    for (int i = 0; i < 2; i++) {
        float inv0 = 1.f / lf[i][0], inv1 = 1.f / lf[i][2];
        int row0 = q0 + rb + i * 16 + g;
        __half* op0 = att_out + ((size_t)(b * TT + row0)) * DM + hh * 64;
        __half* op1 = op0 + (size_t)8 * DM;
        #pragma unroll
        for (int dj = 0; dj < 8; dj++) {
            int col = dj * 8 + 2 * tig;
            *(__half2*)(op0 + col) = __floats2half2_rn(o[i][dj][0] * inv0,
                                                       o[i][dj][1] * inv0);
            *(__half2*)(op1 + col) = __floats2half2_rn(o[i][dj][2] * inv1,
                                                       o[i][dj][3] * inv1);
        }
    }
}

// ---------------------------------------------------------------------------
// Host: tensor map construction (driver entry point via cudart; no -lcuda)
// ---------------------------------------------------------------------------
typedef CUresult (*PFN_tmEncode)(
    CUtensorMap*, CUtensorMapDataType, cuuint32_t, void*,
    const cuuint64_t*, const cuuint64_t*, const cuuint32_t*, const cuuint32_t*,
    CUtensorMapInterleave, CUtensorMapSwizzle, CUtensorMapL2promotion,
    CUtensorMapFloatOOBfill);

static void make_tm(CUtensorMap* tm, void* ptr, uint64_t d0, uint64_t d1) {
    void* fn = nullptr;
    cudaDriverEntryPointQueryResult qr;
    cudaGetDriverEntryPoint("cuTensorMapEncodeTiled", &fn, cudaEnableDefault, &qr);
    cuuint64_t dims[2]    = {d0, d1};
    cuuint64_t strides[1] = {d0 * 2};       // bytes per row
    cuuint32_t box[2]     = {64, 128};      // 64 halves (128B) x 128 rows
    cuuint32_t es[2]      = {1, 1};
    ((PFN_tmEncode)fn)(tm, CU_TENSOR_MAP_DATA_TYPE_FLOAT16, 2, ptr,
                       dims, strides, box, es,
                       CU_TENSOR_MAP_INTERLEAVE_NONE, CU_TENSOR_MAP_SWIZZLE_128B,
                       CU_TENSOR_MAP_L2_PROMOTION_L2_128B,
                       CU_TENSOR_MAP_FLOAT_OOB_FILL_NONE);
}

// ---------------------------------------------------------------------------
// kernel_launch
// Inputs: 0:x  1:mask(unused)  2:freqs_cos  3:freqs_sin
//         4:qkv_w  5:qkv_b  6:proj_w  7:proj_b
// ---------------------------------------------------------------------------
extern "C" void kernel_launch(void* const* d_in, const int* in_sizes, int n_in,
                              void* d_out, int out_size) {
    const float* x      = (const float*)d_in[0];
    const float* fcos   = (const float*)d_in[2];
    const float* fsin   = (const float*)d_in[3];
    const float* qkv_w  = (const float*)d_in[4];
    const float* qkv_b  = (const float*)d_in[5];
    const float* proj_w = (const float*)d_in[6];
    const float* proj_b = (const float*)d_in[7];
    float* out = (float*)d_out;

    __half *qkv2, *att, *x16, *wq, *wp;
    cudaGetSymbolAddress((void**)&qkv2, g_qkv2);
    cudaGetSymbolAddress((void**)&att,  g_att);
    cudaGetSymbolAddress((void**)&x16,  g_x16);
    cudaGetSymbolAddress((void**)&wq,   g_wq);
    cudaGetSymbolAddress((void**)&wp,   g_wp);

    cudaFuncSetAttribute(gemm_tc, cudaFuncAttributeMaxDynamicSharedMemorySize,
                         GSMEM_TOTAL);
    cudaFuncSetAttribute(attn_tc, cudaFuncAttributeMaxDynamicSharedMemorySize,
                         ASMEM_TOTAL);

    const int M = BB * TT;   // 8192

    CUtensorMap tmX, tmWq, tmAtt, tmWp;
    make_tm(&tmX,   x16, DM, M);
    make_tm(&tmWq,  wq,  DM, 3 * DM);
    make_tm(&tmAtt, att, DM, M);
    make_tm(&tmWp,  wp,  DM, DM);

    // 0) operand prep: fp32 -> fp16
    prep_plain<<<(M * DM / 8) / 256, 256>>>(x, x16, M * DM / 8);
    prep_plain<<<(3 * DM * DM / 8) / 256, 256>>>(qkv_w, wq, 3 * DM * DM / 8);
    prep_plain<<<(DM * DM / 8) / 256, 256>>>(proj_w, wp, DM * DM / 8);

    // 1) QKV GEMM (TMA staging) with fused rope epilogue -> qkv2 (fp16)
    {
        dim3 grid(3 * DM / 128, M / 128);
        gemm_tc<<<grid, 256, GSMEM_TOTAL>>>(tmX, tmWq, qkv_b, qkv2, M, 3 * DM, DM,
                                            1, fcos, fsin);
    }
    // 2) causal attention -> att (fp16)
    {
        dim3 grid(TT / 128, BB * NH);
        attn_tc<<<grid, 128, ASMEM_TOTAL>>>(qkv2, att);
    }
    // 3) output projection (TMA staging) -> d_out (fp32)
    {
        dim3 grid(DM / 128, M / 128);
        gemm_tc<<<grid, 256, GSMEM_TOTAL>>>(tmAtt, tmWp, proj_b, out, M, DM, DM,
                                            0, nullptr, nullptr);
    }
}

// round 16
// speedup vs baseline: 1.1477x; 1.0061x over previous
#include <cuda_runtime.h>
#include <cuda.h>
#include <cuda_fp16.h>
#include <math_constants.h>
#include <cstdint>

#define BB 4
#define TT 2048
#define DM 1024
#define NH 16
#define DH 64

// Scratch (plain fp16 row-major; ldmatrix handles fragment distribution)
__device__ __half g_qkv2[(size_t)BB * TT * 3 * DM]; // q(rope*scale*log2e), k(rope), v
__device__ __half g_att [(size_t)BB * TT * DM];     // attention out
__device__ __half g_x16 [(size_t)BB * TT * DM];     // x fp16
__device__ __half g_wq  [(size_t)3 * DM * DM];      // qkv_w fp16
__device__ __half g_wp  [(size_t)DM * DM];          // proj_w fp16

// ===========================================================================
// Helpers
// ===========================================================================
__device__ __forceinline__ uint32_t packh2(float x, float y) {
    __half2 h = __floats2half2_rn(x, y);
    return *reinterpret_cast<uint32_t*>(&h);
}

__device__ __forceinline__ uint32_t pexp2(float x, float y) {
    __half2 h = h2exp2(__floats2half2_rn(x, y));
    return *reinterpret_cast<uint32_t*>(&h);
}

// D += A(16x16,row) * B(16x8,col), fp16 inputs, fp32 accum
__device__ __forceinline__ void mma16(float* c, const uint32_t* a,
                                      uint32_t b0, uint32_t b1) {
    asm volatile(
        "mma.sync.aligned.m16n8k16.row.col.f32.f16.f16.f32 "
        "{%0,%1,%2,%3}, {%4,%5,%6,%7}, {%8,%9}, {%0,%1,%2,%3};"
        : "+f"(c[0]), "+f"(c[1]), "+f"(c[2]), "+f"(c[3])
        : "r"(a[0]), "r"(a[1]), "r"(a[2]), "r"(a[3]), "r"(b0), "r"(b1));
}

__device__ __forceinline__ void ldm_x4(uint32_t* r, uint32_t addr) {
    asm volatile("ldmatrix.sync.aligned.m8n8.x4.shared.b16 {%0,%1,%2,%3}, [%4];"
                 : "=r"(r[0]), "=r"(r[1]), "=r"(r[2]), "=r"(r[3]) : "r"(addr));
}

__device__ __forceinline__ void ldm_x4_t(uint32_t* r, uint32_t addr) {
    asm volatile("ldmatrix.sync.aligned.m8n8.x4.trans.shared.b16 {%0,%1,%2,%3}, [%4];"
                 : "=r"(r[0]), "=r"(r[1]), "=r"(r[2]), "=r"(r[3]) : "r"(addr));
}

__device__ __forceinline__ uint32_t smem_u32(const void* p) {
    uint32_t a;
    asm("{ .reg .u64 t; cvta.to.shared.u64 t, %1; cvt.u32.u64 %0, t; }"
        : "=r"(a) : "l"(p));
    return a;
}

// --- TMA / mbarrier ---
__device__ __forceinline__ void tma2d(uint32_t dst, const CUtensorMap* tm,
                                      int cx, int cy, uint32_t mb) {
    asm volatile(
        "cp.async.bulk.tensor.2d.shared::cta.global.tile.mbarrier::complete_tx::bytes "
        "[%0], [%1, {%2, %3}], [%4];"
        :: "r"(dst), "l"(tm), "r"(cx), "r"(cy), "r"(mb) : "memory");
}
__device__ __forceinline__ void mbar_init(uint32_t mb, uint32_t cnt) {
    asm volatile("mbarrier.init.shared.b64 [%0], %1;" :: "r"(mb), "r"(cnt) : "memory");
}
__device__ __forceinline__ void mbar_expect(uint32_t mb, uint32_t bytes) {
    asm volatile("mbarrier.arrive.expect_tx.shared.b64 _, [%0], %1;"
                 :: "r"(mb), "r"(bytes) : "memory");
}
__device__ __forceinline__ void mbar_wait(uint32_t mb, uint32_t parity) {
    asm volatile(
        "{\n\t.reg .pred P;\n\t"
        "WAIT_%=:\n\t"
        "mbarrier.try_wait.parity.shared::cta.b64 P, [%0], %1, 0x989680;\n\t"
        "@P bra.uni DONE_%=;\n\t"
        "bra.uni WAIT_%=;\n\t"
        "DONE_%=:\n\t}"
        :: "r"(mb), "r"(parity) : "memory");
}

// ===========================================================================
// prep_plain: fp32 -> fp16, 8 consecutive elements per thread
// ===========================================================================
__global__ void prep_plain(const float* __restrict__ src, __half* __restrict__ dst,
                           int n8) {
    int i = blockIdx.x * blockDim.x + threadIdx.x;
    if (i >= n8) return;
    const float4* s = (const float4*)src + (size_t)i * 2;
    float4 f0 = s[0], f1 = s[1];
    uint4 o;
    o.x = packh2(f0.x, f0.y); o.y = packh2(f0.z, f0.w);
    o.z = packh2(f1.x, f1.y); o.w = packh2(f1.z, f1.w);
    *((uint4*)(dst + (size_t)i * 8)) = o;
}

// ===========================================================================
// GEMM (R15 config): TMA staging, 3-stage mbarrier pipeline, CTA 128x128,
// 8 warps (4m x 2n), warp 32x64, ldmatrix.x4 fragments, 2 CTAs/SM.
// mode 0: fp32 out. mode 1: fused qkv rope/scale epilogue (fp16 out).
// ===========================================================================
#define GTILEB 16384                            // bytes per operand tile
#define GSMEM_TOTAL (6 * GTILEB + 1024 + 64)    // tiles + align slack + mbars

__global__ void __launch_bounds__(256, 2)
gemm_tc(const __grid_constant__ CUtensorMap tmA,
        const __grid_constant__ CUtensorMap tmB,
        const float* __restrict__ bias, void* __restrict__ Cv,
        int M, int N, int K, int mode,
        const float* __restrict__ fcos, const float* __restrict__ fsin) {
    extern __shared__ uint32_t gsm[];
    const uint32_t ab   = (smem_u32(gsm) + 1023u) & ~1023u;
    const uint32_t mbar = ab + 6 * GTILEB;

    const int tid  = threadIdx.x;
    const int wid  = tid >> 5;
    const int lane = tid & 31;
    const int g    = lane >> 2;
    const int tig  = lane & 3;
    const int wm   = wid & 3;
    const int wn   = wid >> 2;

    const int m0 = blockIdx.y * 128;
    const int n0 = blockIdx.x * 128;

    const int l8  = lane & 7;
    const int lA8 = ((lane >> 3) & 1) * 8;
    const int lhi = lane >> 4;
    const int bhi = (lane >> 3) & 1;
    const int bA8 = lhi * 8;
    uint32_t aOff[2][4], bOff[4][4];
    #pragma unroll
    for (int i = 0; i < 2; i++) {
        int r = wm * 32 + i * 16 + l8 + lA8;
        #pragma unroll
        for (int s = 0; s < 4; s++)
            aOff[i][s] = r * 128 + (((2 * s + lhi) ^ (r & 7)) << 4);
    }
    #pragma unroll
    for (int p = 0; p < 4; p++) {
        int r = wn * 64 + 16 * p + l8 + bA8;
        #pragma unroll
        for (int s = 0; s < 4; s++)
            bOff[p][s] = r * 128 + (((2 * s + bhi) ^ (r & 7)) << 4);
    }

    if (tid == 0) {
        mbar_init(mbar, 1);
        mbar_init(mbar + 8, 1);
        mbar_init(mbar + 16, 1);
    }
    __syncthreads();

    float acc[2][8][4];
    #pragma unroll
    for (int i = 0; i < 2; i++)
        #pragma unroll
        for (int j = 0; j < 8; j++)
            #pragma unroll
            for (int e = 0; e < 4; e++) acc[i][j][e] = 0.f;

    const int NK = K >> 6;

    auto load_stage = [&](int st, int k0) {
        if (tid == 0) {
            uint32_t mb = mbar + st * 8;
            mbar_expect(mb, 2 * GTILEB);
            tma2d(ab + st * 2 * GTILEB,          &tmA, k0, m0, mb);
            tma2d(ab + st * 2 * GTILEB + GTILEB, &tmB, k0, n0, mb);
        }
    };

    load_stage(0, 0);
    load_stage(1, 64);

    int ph0 = 0, ph1 = 0, ph2 = 0;
    int cur = 0, pre = 2;
    for (int kt = 0; kt < NK; kt++) {
        if (cur == 0)      { mbar_wait(mbar,      ph0); ph0 ^= 1; }
        else if (cur == 1) { mbar_wait(mbar + 8,  ph1); ph1 ^= 1; }
        else               { mbar_wait(mbar + 16, ph2); ph2 ^= 1; }
        __syncthreads();

        if (kt + 2 < NK) load_stage(pre, (kt + 2) << 6);

        const uint32_t aBase = ab + cur * 2 * GTILEB;
        const uint32_t bBase = aBase + GTILEB;

        #pragma unroll
        for (int s = 0; s < 4; s++) {
            uint32_t a[2][4], bf[4][4];
            #pragma unroll
            for (int i = 0; i < 2; i++) ldm_x4(a[i], aBase + aOff[i][s]);
            #pragma unroll
            for (int p = 0; p < 4; p++) ldm_x4(bf[p], bBase + bOff[p][s]);
            #pragma unroll
            for (int j = 0; j < 8; j++) {
                uint32_t b0 = bf[j >> 1][(j & 1) * 2];
                uint32_t b1 = bf[j >> 1][(j & 1) * 2 + 1];
                #pragma unroll
                for (int i = 0; i < 2; i++) mma16(acc[i][j], a[i], b0, b1);
            }
        }

        cur = (cur == 2) ? 0 : cur + 1;
        pre = (pre == 2) ? 0 : pre + 1;
    }

    #pragma unroll
    for (int i = 0; i < 2; i++) {
        int row0 = m0 + wm * 32 + i * 16 + g;
        int row1 = row0 + 8;
        #pragma unroll
        for (int j = 0; j < 8; j++) {
            int col = n0 + wn * 64 + j * 8 + 2 * tig;
            float bv0 = bias[col], bv1 = bias[col + 1];
            float v00 = acc[i][j][0] + bv0, v01 = acc[i][j][1] + bv1;
            float v10 = acc[i][j][2] + bv0, v11 = acc[i][j][3] + bv1;
            if (mode == 0) {
                float* C = (float*)Cv;
                *(float2*)(C + (size_t)row0 * N + col) = make_float2(v00, v01);
                *(float2*)(C + (size_t)row1 * N + col) = make_float2(v10, v11);
            } else {
                __half* C = (__half*)Cv;
                int sec = col >> 10;
                int d   = col & 63;
                if (sec < 2) {
                    float sc = (sec == 0) ? 0.18033688011112042f : 1.f;
                    int t0i = row0 & (TT - 1), t1i = row1 & (TT - 1);
                    float c0 = fcos[t0i * 32 + (d >> 1)], s0 = fsin[t0i * 32 + (d >> 1)];
                    float c1 = fcos[t1i * 32 + (d >> 1)], s1 = fsin[t1i * 32 + (d >> 1)];
                    *(__half2*)(C + (size_t)row0 * N + col) =
                        __floats2half2_rn((v00 * c0 - v01 * s0) * sc,
                                          (v00 * s0 + v01 * c0) * sc);
                    *(__half2*)(C + (size_t)row1 * N + col) =
                        __floats2half2_rn((v10 * c1 - v11 * s1) * sc,
                                          (v10 * s1 + v11 * c1) * sc);
                } else {
                    *(__half2*)(C + (size_t)row0 * N + col) = __floats2half2_rn(v00, v01);
                    *(__half2*)(C + (size_t)row1 * N + col) = __floats2half2_rn(v10, v11);
                }
            }
        }
    }
}

// ===========================================================================
// Flash attention v15: TMA staging for Q and K/V, 128-q blocks, 128 threads
// (4 warps x 32 rows), 2 CTAs/SM, 64-key double-buffered mbarrier pipeline.
// V via ldmatrix.trans. log2 softmax, fp16x2 exp2, ones-MMA row sums.
// ===========================================================================
#define QB 16384                           // Q tile bytes (128 x 128B)
#define KVB 8192                           // K or V tile bytes (64 x 128B)
#define ASMEM_TOTAL (QB + 4 * KVB + 1024 + 64)
#define ONESH2 0x3C003C00u

__global__ void __launch_bounds__(128, 2)
attn_tc(const __grid_constant__ CUtensorMap tmQ,
        const __grid_constant__ CUtensorMap tmKV,
        __half* __restrict__ att_out) {
    extern __shared__ uint32_t asmw[];
    const uint32_t sbase = (smem_u32(asmw) + 1023u) & ~1023u;
    const uint32_t mbar  = sbase + QB + 4 * KVB;   // [0]=Q, [8]=kv0, [16]=kv1

    const int tid  = threadIdx.x;
    const int w    = tid >> 5;
    const int lane = tid & 31;
    const int g    = lane >> 2;
    const int tig  = lane & 3;
    const int rb   = w * 32;

    const int b   = blockIdx.y >> 4;
    const int hh  = blockIdx.y & 15;
    const int bxx = gridDim.x - 1 - blockIdx.x;   // longest blocks first
    const int q0  = bxx * 128;
    const int bT  = b * TT;

    // ldmatrix lane offsets
    const int l8  = lane & 7;
    const int lA8 = ((lane >> 3) & 1) * 8;
    const int lhi = lane >> 4;
    const int bhi = (lane >> 3) & 1;
    const int bA8 = lhi * 8;
    uint32_t kOff[4][4], vOff[4][4];
    #pragma unroll
    for (int p = 0; p < 4; p++) {
        int r = 16 * p + l8 + bA8;
        #pragma unroll
        for (int s = 0; s < 4; s++)
            kOff[p][s] = r * 128 + (((2 * s + bhi) ^ (r & 7)) << 4);
    }
    #pragma unroll
    for (int e = 0; e < 4; e++) {
        #pragma unroll
        for (int s = 0; s < 4; s++) {
            int r = 16 * s + l8 + lA8;
            vOff[e][s] = r * 128 + (((2 * e + lhi) ^ (r & 7)) << 4);
        }
    }

    if (tid == 0) {
        mbar_init(mbar, 1);
        mbar_init(mbar + 8, 1);
        mbar_init(mbar + 16, 1);
    }
    __syncthreads();

    // stage Q + first K/V tile
    auto stage_kv = [&](int buf, int j0) {
        if (tid == 0) {
            uint32_t mb = mbar + 8 + buf * 8;
            mbar_expect(mb, 2 * KVB);
            tma2d(sbase + QB + buf * KVB,       &tmKV, DM + hh * 64,     bT + j0, mb);
            tma2d(sbase + QB + (2 + buf) * KVB, &tmKV, 2 * DM + hh * 64, bT + j0, mb);
        }
    };

    if (tid == 0) {
        mbar_expect(mbar, QB);
        tma2d(sbase, &tmQ, hh * 64, bT + q0, mbar);
    }
    stage_kv(0, 0);

    mbar_wait(mbar, 0);   // Q landed
    __syncthreads();

    // --- Q fragments (once) ---
    uint32_t qa[2][4][4];
    #pragma unroll
    for (int i = 0; i < 2; i++) {
        int r = rb + i * 16 + l8 + lA8;
        #pragma unroll
        for (int s = 0; s < 4; s++)
            ldm_x4(qa[i][s], sbase + r * 128 + (((2 * s + lhi) ^ (r & 7)) << 4));
    }

    float o[2][8][4];
    #pragma unroll
    for (int i = 0; i < 2; i++)
        #pragma unroll
        for (int j = 0; j < 8; j++)
            #pragma unroll
            for (int e = 0; e < 4; e++) o[i][j][e] = 0.f;
    float lf[2][4] = {{0.f, 0.f, 0.f, 0.f}, {0.f, 0.f, 0.f, 0.f}};
    float mv[2][2] = {{-CUDART_INF_F, -CUDART_INF_F}, {-CUDART_INF_F, -CUDART_INF_F}};

    const int ntiles = 2 * (bxx + 1);
    int phv[2] = {0, 0};

    for (int tile = 0; tile < ntiles; tile++) {
        const int j0  = tile * 64;
        const int cur = tile & 1;

        if (tile + 1 < ntiles) stage_kv(cur ^ 1, j0 + 64);

        mbar_wait(mbar + 8 + cur * 8, phv[cur]);
        phv[cur] ^= 1;
        __syncthreads();

        const uint32_t kBase = sbase + QB + cur * KVB;
        const uint32_t vBase = sbase + QB + (2 + cur) * KVB;
        const bool active = (j0 <= q0 + rb + 31);

        if (active) {
            // --- S = Q @ K^T (log2 domain) ---
            float p[2][8][4];
            #pragma unroll
            for (int i = 0; i < 2; i++)
                #pragma unroll
                for (int j = 0; j < 8; j++)
                    #pragma unroll
                    for (int e = 0; e < 4; e++) p[i][j][e] = 0.f;
            #pragma unroll
            for (int s = 0; s < 4; s++) {
                uint32_t bf[4][4];
                #pragma unroll
                for (int pp = 0; pp < 4; pp++) ldm_x4(bf[pp], kBase + kOff[pp][s]);
                #pragma unroll
                for (int j = 0; j < 8; j++) {
                    uint32_t b0 = bf[j >> 1][(j & 1) * 2];
                    uint32_t b1 = bf[j >> 1][(j & 1) * 2 + 1];
                    mma16(p[0][j], qa[0][s], b0, b1);
                    mma16(p[1][j], qa[1][s], b0, b1);
                }
            }

            // --- causal mask on diagonal tiles ---
            if (j0 + 63 > q0 + rb) {
                #pragma unroll
                for (int i = 0; i < 2; i++) {
                    int row0 = q0 + rb + i * 16 + g;
                    int row1 = row0 + 8;
                    #pragma unroll
                    for (int j = 0; j < 8; j++) {
                        int col = j0 + j * 8 + 2 * tig;
                        if (col > row0)     p[i][j][0] = -CUDART_INF_F;
                        if (col + 1 > row0) p[i][j][1] = -CUDART_INF_F;
                        if (col > row1)     p[i][j][2] = -CUDART_INF_F;
                        if (col + 1 > row1) p[i][j][3] = -CUDART_INF_F;
                    }
                }
            }

            // --- online max update + rescale ---
            #pragma unroll
            for (int i = 0; i < 2; i++) {
                float r0 = -CUDART_INF_F, r1 = -CUDART_INF_F;
                #pragma unroll
                for (int j = 0; j < 8; j++) {
                    r0 = fmaxf(r0, fmaxf(p[i][j][0], p[i][j][1]));
                    r1 = fmaxf(r1, fmaxf(p[i][j][2], p[i][j][3]));
                }
                r0 = fmaxf(r0, __shfl_xor_sync(0xffffffffu, r0, 1));
                r0 = fmaxf(r0, __shfl_xor_sync(0xffffffffu, r0, 2));
                r1 = fmaxf(r1, __shfl_xor_sync(0xffffffffu, r1, 1));
                r1 = fmaxf(r1, __shfl_xor_sync(0xffffffffu, r1, 2));
                float nm0 = fmaxf(mv[i][0], r0);
                float nm1 = fmaxf(mv[i][1], r1);
                float sc0 = exp2f(mv[i][0] - nm0);
                float sc1 = exp2f(mv[i][1] - nm1);
                mv[i][0] = nm0; mv[i][1] = nm1;
                lf[i][0] *= sc0; lf[i][2] *= sc1;
                #pragma unroll
                for (int j = 0; j < 8; j++) {
                    o[i][j][0] *= sc0; o[i][j][1] *= sc0;
                    o[i][j][2] *= sc1; o[i][j][3] *= sc1;
                }
            }

            // --- P = exp2(S - m) as fp16 A-frags; l += P@1; O += P@V ---
            #pragma unroll
            for (int s = 0; s < 4; s++) {
                uint32_t pa[2][4];
                #pragma unroll
                for (int i = 0; i < 2; i++) {
                    float nm0 = mv[i][0], nm1 = mv[i][1];
                    pa[i][0] = pexp2(p[i][2 * s][0] - nm0,     p[i][2 * s][1] - nm0);
                    pa[i][1] = pexp2(p[i][2 * s][2] - nm1,     p[i][2 * s][3] - nm1);
                    pa[i][2] = pexp2(p[i][2 * s + 1][0] - nm0, p[i][2 * s + 1][1] - nm0);
                    pa[i][3] = pexp2(p[i][2 * s + 1][2] - nm1, p[i][2 * s + 1][3] - nm1);
                }
                mma16(lf[0], pa[0], ONESH2, ONESH2);
                mma16(lf[1], pa[1], ONESH2, ONESH2);

                uint32_t vf[4][4];
                #pragma unroll
                for (int e = 0; e < 4; e++) ldm_x4_t(vf[e], vBase + vOff[e][s]);
                #pragma unroll
                for (int dj = 0; dj < 8; dj++) {
                    uint32_t b0 = vf[dj >> 1][(dj & 1) * 2];
                    uint32_t b1 = vf[dj >> 1][(dj & 1) * 2 + 1];
                    mma16(o[0][dj], pa[0], b0, b1);
                    mma16(o[1][dj], pa[1], b0, b1);
                }
            }
        }
        __syncthreads();
    }

    // --- normalize + store fp16 ---
    #pragma unroll
    for (int i = 0; i < 2; i++) {
        float inv0 = 1.f / lf[i][0], inv1 = 1.f / lf[i][2];
        int row0 = q0 + rb + i * 16 + g;
        __half* op0 = att_out + ((size_t)(bT + row0)) * DM + hh * 64;
        __half* op1 = op0 + (size_t)8 * DM;
        #pragma unroll
        for (int dj = 0; dj < 8; dj++) {
            int col = dj * 8 + 2 * tig;
            *(__half2*)(op0 + col) = __floats2half2_rn(o[i][dj][0] * inv0,
                                                       o[i][dj][1] * inv0);
            *(__half2*)(op1 + col) = __floats2half2_rn(o[i][dj][2] * inv1,
                                                       o[i][dj][3] * inv1);
        }
    }
}

// ---------------------------------------------------------------------------
// Host: tensor map construction (driver entry point via cudart; no -lcuda)
// ---------------------------------------------------------------------------
typedef CUresult (*PFN_tmEncode)(
    CUtensorMap*, CUtensorMapDataType, cuuint32_t, void*,
    const cuuint64_t*, const cuuint64_t*, const cuuint32_t*, const cuuint32_t*,
    CUtensorMapInterleave, CUtensorMapSwizzle, CUtensorMapL2promotion,
    CUtensorMapFloatOOBfill);

static void make_tm(CUtensorMap* tm, void* ptr, uint64_t d0, uint64_t d1,
                    uint32_t box0, uint32_t box1) {
    void* fn = nullptr;
    cudaDriverEntryPointQueryResult qr;
    cudaGetDriverEntryPoint("cuTensorMapEncodeTiled", &fn, cudaEnableDefault, &qr);
    cuuint64_t dims[2]    = {d0, d1};
    cuuint64_t strides[1] = {d0 * 2};
    cuuint32_t box[2]     = {box0, box1};
    cuuint32_t es[2]      = {1, 1};
    ((PFN_tmEncode)fn)(tm, CU_TENSOR_MAP_DATA_TYPE_FLOAT16, 2, ptr,
                       dims, strides, box, es,
                       CU_TENSOR_MAP_INTERLEAVE_NONE, CU_TENSOR_MAP_SWIZZLE_128B,
                       CU_TENSOR_MAP_L2_PROMOTION_L2_128B,
                       CU_TENSOR_MAP_FLOAT_OOB_FILL_NONE);
}

// ---------------------------------------------------------------------------
// kernel_launch
// Inputs: 0:x  1:mask(unused)  2:freqs_cos  3:freqs_sin
//         4:qkv_w  5:qkv_b  6:proj_w  7:proj_b
// ---------------------------------------------------------------------------
extern "C" void kernel_launch(void* const* d_in, const int* in_sizes, int n_in,
                              void* d_out, int out_size) {
    const float* x      = (const float*)d_in[0];
    const float* fcos   = (const float*)d_in[2];
    const float* fsin   = (const float*)d_in[3];
    const float* qkv_w  = (const float*)d_in[4];
    const float* qkv_b  = (const float*)d_in[5];
    const float* proj_w = (const float*)d_in[6];
    const float* proj_b = (const float*)d_in[7];
    float* out = (float*)d_out;

    __half *qkv2, *att, *x16, *wq, *wp;
    cudaGetSymbolAddress((void**)&qkv2, g_qkv2);
    cudaGetSymbolAddress((void**)&att,  g_att);
    cudaGetSymbolAddress((void**)&x16,  g_x16);
    cudaGetSymbolAddress((void**)&wq,   g_wq);
    cudaGetSymbolAddress((void**)&wp,   g_wp);

    cudaFuncSetAttribute(gemm_tc, cudaFuncAttributeMaxDynamicSharedMemorySize,
                         GSMEM_TOTAL);
    cudaFuncSetAttribute(attn_tc, cudaFuncAttributeMaxDynamicSharedMemorySize,
                         ASMEM_TOTAL);

    const int M = BB * TT;   // 8192

    CUtensorMap tmX, tmWq, tmAtt, tmWp, tmQ, tmKV;
    make_tm(&tmX,   x16,  DM,     M,      64, 128);
    make_tm(&tmWq,  wq,   DM,     3 * DM, 64, 128);
    make_tm(&tmAtt, att,  DM,     M,      64, 128);
    make_tm(&tmWp,  wp,   DM,     DM,     64, 128);
    make_tm(&tmQ,   qkv2, 3 * DM, M,      64, 128);
    make_tm(&tmKV,  qkv2, 3 * DM, M,      64, 64);

    // 0) operand prep: fp32 -> fp16
    prep_plain<<<(M * DM / 8) / 256, 256>>>(x, x16, M * DM / 8);
    prep_plain<<<(3 * DM * DM / 8) / 256, 256>>>(qkv_w, wq, 3 * DM * DM / 8);
    prep_plain<<<(DM * DM / 8) / 256, 256>>>(proj_w, wp, DM * DM / 8);

    // 1) QKV GEMM (TMA) with fused rope epilogue -> qkv2 (fp16)
    {
        dim3 grid(3 * DM / 128, M / 128);
        gemm_tc<<<grid, 256, GSMEM_TOTAL>>>(tmX, tmWq, qkv_b, qkv2, M, 3 * DM, DM,
                                            1, fcos, fsin);
    }
    // 2) causal attention (TMA staging) -> att (fp16)
    {
        dim3 grid(TT / 128, BB * NH);
        attn_tc<<<grid, 128, ASMEM_TOTAL>>>(tmQ, tmKV, att);
    }
    // 3) output projection (TMA) -> d_out (fp32)
    {
        dim3 grid(DM / 128, M / 128);
        gemm_tc<<<grid, 256, GSMEM_TOTAL>>>(tmAtt, tmWp, proj_b, out, M, DM, DM,
                                            0, nullptr, nullptr);
    }
}

// round 17
// speedup vs baseline: 1.1678x; 1.0175x over previous
#include <cuda_runtime.h>
#include <cuda.h>
#include <cuda_fp16.h>
#include <math_constants.h>
#include <cstdint>

#define BB 4
#define TT 2048
#define DM 1024
#define NH 16
#define DH 64

// Scratch (plain fp16 row-major; ldmatrix handles fragment distribution)
__device__ __half g_qkv2[(size_t)BB * TT * 3 * DM]; // q(rope*scale*log2e), k(rope), v
__device__ __half g_att [(size_t)BB * TT * DM];     // attention out
__device__ __half g_x16 [(size_t)BB * TT * DM];     // x fp16
__device__ __half g_wq  [(size_t)3 * DM * DM];      // qkv_w fp16
__device__ __half g_wp  [(size_t)DM * DM];          // proj_w fp16

// ===========================================================================
// Helpers
// ===========================================================================
__device__ __forceinline__ uint32_t packh2(float x, float y) {
    __half2 h = __floats2half2_rn(x, y);
    return *reinterpret_cast<uint32_t*>(&h);
}

__device__ __forceinline__ uint32_t pexp2(float x, float y) {
    __half2 h = h2exp2(__floats2half2_rn(x, y));
    return *reinterpret_cast<uint32_t*>(&h);
}

// D += A(16x16,row) * B(16x8,col), fp16 inputs, fp32 accum
__device__ __forceinline__ void mma16(float* c, const uint32_t* a,
                                      uint32_t b0, uint32_t b1) {
    asm volatile(
        "mma.sync.aligned.m16n8k16.row.col.f32.f16.f16.f32 "
        "{%0,%1,%2,%3}, {%4,%5,%6,%7}, {%8,%9}, {%0,%1,%2,%3};"
        : "+f"(c[0]), "+f"(c[1]), "+f"(c[2]), "+f"(c[3])
        : "r"(a[0]), "r"(a[1]), "r"(a[2]), "r"(a[3]), "r"(b0), "r"(b1));
}

__device__ __forceinline__ void ldm_x4(uint32_t* r, uint32_t addr) {
    asm volatile("ldmatrix.sync.aligned.m8n8.x4.shared.b16 {%0,%1,%2,%3}, [%4];"
                 : "=r"(r[0]), "=r"(r[1]), "=r"(r[2]), "=r"(r[3]) : "r"(addr));
}

__device__ __forceinline__ void ldm_x4_t(uint32_t* r, uint32_t addr) {
    asm volatile("ldmatrix.sync.aligned.m8n8.x4.trans.shared.b16 {%0,%1,%2,%3}, [%4];"
                 : "=r"(r[0]), "=r"(r[1]), "=r"(r[2]), "=r"(r[3]) : "r"(addr));
}

__device__ __forceinline__ uint32_t smem_u32(const void* p) {
    uint32_t a;
    asm("{ .reg .u64 t; cvta.to.shared.u64 t, %1; cvt.u32.u64 %0, t; }"
        : "=r"(a) : "l"(p));
    return a;
}

// --- TMA / mbarrier ---
__device__ __forceinline__ void tma2d(uint32_t dst, const CUtensorMap* tm,
                                      int cx, int cy, uint32_t mb) {
    asm volatile(
        "cp.async.bulk.tensor.2d.shared::cta.global.tile.mbarrier::complete_tx::bytes "
        "[%0], [%1, {%2, %3}], [%4];"
        :: "r"(dst), "l"(tm), "r"(cx), "r"(cy), "r"(mb) : "memory");
}
__device__ __forceinline__ void mbar_init(uint32_t mb, uint32_t cnt) {
    asm volatile("mbarrier.init.shared.b64 [%0], %1;" :: "r"(mb), "r"(cnt) : "memory");
}
__device__ __forceinline__ void mbar_expect(uint32_t mb, uint32_t bytes) {
    asm volatile("mbarrier.arrive.expect_tx.shared.b64 _, [%0], %1;"
                 :: "r"(mb), "r"(bytes) : "memory");
}
__device__ __forceinline__ void mbar_arrive(uint32_t mb) {
    asm volatile("mbarrier.arrive.shared.b64 _, [%0];" :: "r"(mb) : "memory");
}
__device__ __forceinline__ void mbar_wait(uint32_t mb, uint32_t parity) {
    asm volatile(
        "{\n\t.reg .pred P;\n\t"
        "WAIT_%=:\n\t"
        "mbarrier.try_wait.parity.shared::cta.b64 P, [%0], %1, 0x989680;\n\t"
        "@P bra.uni DONE_%=;\n\t"
        "bra.uni WAIT_%=;\n\t"
        "DONE_%=:\n\t}"
        :: "r"(mb), "r"(parity) : "memory");
}

// ===========================================================================
// prep_plain: fp32 -> fp16, 8 consecutive elements per thread
// ===========================================================================
__global__ void prep_plain(const float* __restrict__ src, __half* __restrict__ dst,
                           int n8) {
    int i = blockIdx.x * blockDim.x + threadIdx.x;
    if (i >= n8) return;
    const float4* s = (const float4*)src + (size_t)i * 2;
    float4 f0 = s[0], f1 = s[1];
    uint4 o;
    o.x = packh2(f0.x, f0.y); o.y = packh2(f0.z, f0.w);
    o.z = packh2(f1.x, f1.y); o.w = packh2(f1.z, f1.w);
    *((uint4*)(dst + (size_t)i * 8)) = o;
}

// ===========================================================================
// GEMM v16: TMA staging, 3-stage producer/consumer mbarrier pipeline
// (full cnt=1, empty cnt=8; NO __syncthreads in main loop).
// CTA 128x128, 8 warps (4m x 2n), warp 32x64, ldmatrix.x4, 2 CTAs/SM.
// mode 0: fp32 out. mode 1: fused qkv rope/scale epilogue (fp16 out).
// ===========================================================================
#define GTILEB 16384
#define GSMEM_TOTAL (6 * GTILEB + 1024 + 128)   // tiles + align + 6 mbars

__global__ void __launch_bounds__(256, 2)
gemm_tc(const __grid_constant__ CUtensorMap tmA,
        const __grid_constant__ CUtensorMap tmB,
        const float* __restrict__ bias, void* __restrict__ Cv,
        int M, int N, int K, int mode,
        const float* __restrict__ fcos, const float* __restrict__ fsin) {
    extern __shared__ uint32_t gsm[];
    const uint32_t ab    = (smem_u32(gsm) + 1023u) & ~1023u;
    const uint32_t mfull = ab + 6 * GTILEB;       // full[0..2] at +0,+8,+16
    const uint32_t mempt = mfull + 24;            // empty[0..2] at +0,+8,+16

    const int tid  = threadIdx.x;
    const int wid  = tid >> 5;
    const int lane = tid & 31;
    const int g    = lane >> 2;
    const int tig  = lane & 3;
    const int wm   = wid & 3;
    const int wn   = wid >> 2;

    const int m0 = blockIdx.y * 128;
    const int n0 = blockIdx.x * 128;

    const int l8  = lane & 7;
    const int lA8 = ((lane >> 3) & 1) * 8;
    const int lhi = lane >> 4;
    const int bhi = (lane >> 3) & 1;
    const int bA8 = lhi * 8;
    uint32_t aOff[2][4], bOff[4][4];
    #pragma unroll
    for (int i = 0; i < 2; i++) {
        int r = wm * 32 + i * 16 + l8 + lA8;
        #pragma unroll
        for (int s = 0; s < 4; s++)
            aOff[i][s] = r * 128 + (((2 * s + lhi) ^ (r & 7)) << 4);
    }
    #pragma unroll
    for (int p = 0; p < 4; p++) {
        int r = wn * 64 + 16 * p + l8 + bA8;
        #pragma unroll
        for (int s = 0; s < 4; s++)
            bOff[p][s] = r * 128 + (((2 * s + bhi) ^ (r & 7)) << 4);
    }

    if (tid == 0) {
        #pragma unroll
        for (int s = 0; s < 3; s++) {
            mbar_init(mfull + s * 8, 1);
            mbar_init(mempt + s * 8, 8);
        }
    }
    __syncthreads();

    float acc[2][8][4];
    #pragma unroll
    for (int i = 0; i < 2; i++)
        #pragma unroll
        for (int j = 0; j < 8; j++)
            #pragma unroll
            for (int e = 0; e < 4; e++) acc[i][j][e] = 0.f;

    const int NK = K >> 6;

    auto fill = [&](int st, int k0) {
        uint32_t mb = mfull + st * 8;
        mbar_expect(mb, 2 * GTILEB);
        tma2d(ab + st * 2 * GTILEB,          &tmA, k0, m0, mb);
        tma2d(ab + st * 2 * GTILEB + GTILEB, &tmB, k0, n0, mb);
    };

    if (tid == 0) {              // prologue fills (rounds 0, no empty wait)
        fill(0, 0);
        fill(1, 64);
    }

    int phF0 = 0, phF1 = 0, phF2 = 0;
    int phE0 = 0, phE1 = 0, phE2 = 0;

    for (int kt = 0; kt < NK; kt++) {
        const int st = kt % 3;

        // producer: refill stage (kt+2)%3 after its previous consumers drained
        if (tid == 0 && kt + 2 < NK) {
            int sf = (kt + 2) % 3;
            if (kt + 2 >= 3) {
                if (sf == 0)      { mbar_wait(mempt,      phE0); phE0 ^= 1; }
                else if (sf == 1) { mbar_wait(mempt + 8,  phE1); phE1 ^= 1; }
                else              { mbar_wait(mempt + 16, phE2); phE2 ^= 1; }
            }
            fill(sf, (kt + 2) << 6);
        }

        // consumer: wait stage data
        if (st == 0)      { mbar_wait(mfull,      phF0); phF0 ^= 1; }
        else if (st == 1) { mbar_wait(mfull + 8,  phF1); phF1 ^= 1; }
        else              { mbar_wait(mfull + 16, phF2); phF2 ^= 1; }

        const uint32_t aBase = ab + st * 2 * GTILEB;
        const uint32_t bBase = aBase + GTILEB;

        #pragma unroll
        for (int s = 0; s < 4; s++) {
            uint32_t a[2][4], bf[4][4];
            #pragma unroll
            for (int i = 0; i < 2; i++) ldm_x4(a[i], aBase + aOff[i][s]);
            #pragma unroll
            for (int p = 0; p < 4; p++) ldm_x4(bf[p], bBase + bOff[p][s]);
            #pragma unroll
            for (int j = 0; j < 8; j++) {
                uint32_t b0 = bf[j >> 1][(j & 1) * 2];
                uint32_t b1 = bf[j >> 1][(j & 1) * 2 + 1];
                #pragma unroll
                for (int i = 0; i < 2; i++) mma16(acc[i][j], a[i], b0, b1);
            }
        }

        if (lane == 0) mbar_arrive(mempt + st * 8);   // warp done with stage
    }

    #pragma unroll
    for (int i = 0; i < 2; i++) {
        int row0 = m0 + wm * 32 + i * 16 + g;
        int row1 = row0 + 8;
        #pragma unroll
        for (int j = 0; j < 8; j++) {
            int col = n0 + wn * 64 + j * 8 + 2 * tig;
            float bv0 = bias[col], bv1 = bias[col + 1];
            float v00 = acc[i][j][0] + bv0, v01 = acc[i][j][1] + bv1;
            float v10 = acc[i][j][2] + bv0, v11 = acc[i][j][3] + bv1;
            if (mode == 0) {
                float* C = (float*)Cv;
                *(float2*)(C + (size_t)row0 * N + col) = make_float2(v00, v01);
                *(float2*)(C + (size_t)row1 * N + col) = make_float2(v10, v11);
            } else {
                __half* C = (__half*)Cv;
                int sec = col >> 10;
                int d   = col & 63;
                if (sec < 2) {
                    float sc = (sec == 0) ? 0.18033688011112042f : 1.f;
                    int t0i = row0 & (TT - 1), t1i = row1 & (TT - 1);
                    float c0 = fcos[t0i * 32 + (d >> 1)], s0 = fsin[t0i * 32 + (d >> 1)];
                    float c1 = fcos[t1i * 32 + (d >> 1)], s1 = fsin[t1i * 32 + (d >> 1)];
                    *(__half2*)(C + (size_t)row0 * N + col) =
                        __floats2half2_rn((v00 * c0 - v01 * s0) * sc,
                                          (v00 * s0 + v01 * c0) * sc);
                    *(__half2*)(C + (size_t)row1 * N + col) =
                        __floats2half2_rn((v10 * c1 - v11 * s1) * sc,
                                          (v10 * s1 + v11 * c1) * sc);
                } else {
                    *(__half2*)(C + (size_t)row0 * N + col) = __floats2half2_rn(v00, v01);
                    *(__half2*)(C + (size_t)row1 * N + col) = __floats2half2_rn(v10, v11);
                }
            }
        }
    }
}

// ===========================================================================
// Flash attention v16: TMA staging + producer/consumer mbarrier ring
// (full cnt=1, empty cnt=4; NO __syncthreads in main loop).
// 128-q blocks, 128 threads (4 warps x 32 rows), 2 CTAs/SM, 64-key tiles.
// V via ldmatrix.trans. log2 softmax, fp16x2 exp2, ones-MMA row sums.
// ===========================================================================
#define QB 16384
#define KVB 8192
#define ASMEM_TOTAL (QB + 4 * KVB + 1024 + 128)
#define ONESH2 0x3C003C00u

__global__ void __launch_bounds__(128, 2)
attn_tc(const __grid_constant__ CUtensorMap tmQ,
        const __grid_constant__ CUtensorMap tmKV,
        __half* __restrict__ att_out) {
    extern __shared__ uint32_t asmw[];
    const uint32_t sbase = (smem_u32(asmw) + 1023u) & ~1023u;
    const uint32_t mq    = sbase + QB + 4 * KVB;  // Q full
    const uint32_t mfull = mq + 8;                // kv full[0..1] at +0,+8
    const uint32_t mempt = mfull + 16;            // kv empty[0..1] at +0,+8

    const int tid  = threadIdx.x;
    const int w    = tid >> 5;
    const int lane = tid & 31;
    const int g    = lane >> 2;
    const int tig  = lane & 3;
    const int rb   = w * 32;

    const int b   = blockIdx.y >> 4;
    const int hh  = blockIdx.y & 15;
    const int bxx = gridDim.x - 1 - blockIdx.x;   // longest blocks first
    const int q0  = bxx * 128;
    const int bT  = b * TT;

    // ldmatrix lane offsets
    const int l8  = lane & 7;
    const int lA8 = ((lane >> 3) & 1) * 8;
    const int lhi = lane >> 4;
    const int bhi = (lane >> 3) & 1;
    const int bA8 = lhi * 8;
    uint32_t kOff[4][4], vOff[4][4];
    #pragma unroll
    for (int p = 0; p < 4; p++) {
        int r = 16 * p + l8 + bA8;
        #pragma unroll
        for (int s = 0; s < 4; s++)
            kOff[p][s] = r * 128 + (((2 * s + bhi) ^ (r & 7)) << 4);
    }
    #pragma unroll
    for (int e = 0; e < 4; e++) {
        #pragma unroll
        for (int s = 0; s < 4; s++) {
            int r = 16 * s + l8 + lA8;
            vOff[e][s] = r * 128 + (((2 * e + lhi) ^ (r & 7)) << 4);
        }
    }

    if (tid == 0) {
        mbar_init(mq, 1);
        mbar_init(mfull, 1);     mbar_init(mfull + 8, 1);
        mbar_init(mempt, 4);     mbar_init(mempt + 8, 4);
    }
    __syncthreads();

    auto fill_kv = [&](int buf, int j0) {
        uint32_t mb = mfull + buf * 8;
        mbar_expect(mb, 2 * KVB);
        tma2d(sbase + QB + buf * KVB,       &tmKV, DM + hh * 64,     bT + j0, mb);
        tma2d(sbase + QB + (2 + buf) * KVB, &tmKV, 2 * DM + hh * 64, bT + j0, mb);
    };

    if (tid == 0) {
        mbar_expect(mq, QB);
        tma2d(sbase, &tmQ, hh * 64, bT + q0, mq);
        fill_kv(0, 0);
    }

    mbar_wait(mq, 0);   // Q landed (per-warp wait; no CTA sync needed)

    // --- Q fragments (once) ---
    uint32_t qa[2][4][4];
    #pragma unroll
    for (int i = 0; i < 2; i++) {
        int r = rb + i * 16 + l8 + lA8;
        #pragma unroll
        for (int s = 0; s < 4; s++)
            ldm_x4(qa[i][s], sbase + r * 128 + (((2 * s + lhi) ^ (r & 7)) << 4));
    }

    float o[2][8][4];
    #pragma unroll
    for (int i = 0; i < 2; i++)
        #pragma unroll
        for (int j = 0; j < 8; j++)
            #pragma unroll
            for (int e = 0; e < 4; e++) o[i][j][e] = 0.f;
    float lf[2][4] = {{0.f, 0.f, 0.f, 0.f}, {0.f, 0.f, 0.f, 0.f}};
    float mv[2][2] = {{-CUDART_INF_F, -CUDART_INF_F}, {-CUDART_INF_F, -CUDART_INF_F}};

    const int ntiles = 2 * (bxx + 1);
    int phF[2] = {0, 0};
    int phE[2] = {0, 0};

    for (int tile = 0; tile < ntiles; tile++) {
        const int j0  = tile * 64;
        const int cur = tile & 1;

        // producer: refill other buffer once its previous consumers drained
        if (tid == 0 && tile + 1 < ntiles) {
            int nb = cur ^ 1;
            if (tile + 1 >= 2) {
                mbar_wait(mempt + nb * 8, phE[nb]);
                phE[nb] ^= 1;
            }
            fill_kv(nb, j0 + 64);
        }

        mbar_wait(mfull + cur * 8, phF[cur]);
        phF[cur] ^= 1;

        const uint32_t kBase = sbase + QB + cur * KVB;
        const uint32_t vBase = sbase + QB + (2 + cur) * KVB;
        const bool active = (j0 <= q0 + rb + 31);

        if (active) {
            // --- S = Q @ K^T (log2 domain) ---
            float p[2][8][4];
            #pragma unroll
            for (int i = 0; i < 2; i++)
                #pragma unroll
                for (int j = 0; j < 8; j++)
                    #pragma unroll
                    for (int e = 0; e < 4; e++) p[i][j][e] = 0.f;
            #pragma unroll
            for (int s = 0; s < 4; s++) {
                uint32_t bf[4][4];
                #pragma unroll
                for (int pp = 0; pp < 4; pp++) ldm_x4(bf[pp], kBase + kOff[pp][s]);
                #pragma unroll
                for (int j = 0; j < 8; j++) {
                    uint32_t b0 = bf[j >> 1][(j & 1) * 2];
                    uint32_t b1 = bf[j >> 1][(j & 1) * 2 + 1];
                    mma16(p[0][j], qa[0][s], b0, b1);
                    mma16(p[1][j], qa[1][s], b0, b1);
                }
            }

            // --- causal mask on diagonal tiles ---
            if (j0 + 63 > q0 + rb) {
                #pragma unroll
                for (int i = 0; i < 2; i++) {
                    int row0 = q0 + rb + i * 16 + g;
                    int row1 = row0 + 8;
                    #pragma unroll
                    for (int j = 0; j < 8; j++) {
                        int col = j0 + j * 8 + 2 * tig;
                        if (col > row0)     p[i][j][0] = -CUDART_INF_F;
                        if (col + 1 > row0) p[i][j][1] = -CUDART_INF_F;
                        if (col > row1)     p[i][j][2] = -CUDART_INF_F;
                        if (col + 1 > row1) p[i][j][3] = -CUDART_INF_F;
                    }
                }
            }

            // --- online max update + rescale ---
            #pragma unroll
            for (int i = 0; i < 2; i++) {
                float r0 = -CUDART_INF_F, r1 = -CUDART_INF_F;
                #pragma unroll
                for (int j = 0; j < 8; j++) {
                    r0 = fmaxf(r0, fmaxf(p[i][j][0], p[i][j][1]));
                    r1 = fmaxf(r1, fmaxf(p[i][j][2], p[i][j][3]));
                }
                r0 = fmaxf(r0, __shfl_xor_sync(0xffffffffu, r0, 1));
                r0 = fmaxf(r0, __shfl_xor_sync(0xffffffffu, r0, 2));
                r1 = fmaxf(r1, __shfl_xor_sync(0xffffffffu, r1, 1));
                r1 = fmaxf(r1, __shfl_xor_sync(0xffffffffu, r1, 2));
                float nm0 = fmaxf(mv[i][0], r0);
                float nm1 = fmaxf(mv[i][1], r1);
                float sc0 = exp2f(mv[i][0] - nm0);
                float sc1 = exp2f(mv[i][1] - nm1);
                mv[i][0] = nm0; mv[i][1] = nm1;
                lf[i][0] *= sc0; lf[i][2] *= sc1;
                #pragma unroll
                for (int j = 0; j < 8; j++) {
                    o[i][j][0] *= sc0; o[i][j][1] *= sc0;
                    o[i][j][2] *= sc1; o[i][j][3] *= sc1;
                }
            }

            // --- P = exp2(S - m) as fp16 A-frags; l += P@1; O += P@V ---
            #pragma unroll
            for (int s = 0; s < 4; s++) {
                uint32_t pa[2][4];
                #pragma unroll
                for (int i = 0; i < 2; i++) {
                    float nm0 = mv[i][0], nm1 = mv[i][1];
                    pa[i][0] = pexp2(p[i][2 * s][0] - nm0,     p[i][2 * s][1] - nm0);
                    pa[i][1] = pexp2(p[i][2 * s][2] - nm1,     p[i][2 * s][3] - nm1);
                    pa[i][2] = pexp2(p[i][2 * s + 1][0] - nm0, p[i][2 * s + 1][1] - nm0);
                    pa[i][3] = pexp2(p[i][2 * s + 1][2] - nm1, p[i][2 * s + 1][3] - nm1);
                }
                mma16(lf[0], pa[0], ONESH2, ONESH2);
                mma16(lf[1], pa[1], ONESH2, ONESH2);

                uint32_t vf[4][4];
                #pragma unroll
                for (int e = 0; e < 4; e++) ldm_x4_t(vf[e], vBase + vOff[e][s]);
                #pragma unroll
                for (int dj = 0; dj < 8; dj++) {
                    uint32_t b0 = vf[dj >> 1][(dj & 1) * 2];
                    uint32_t b1 = vf[dj >> 1][(dj & 1) * 2 + 1];
                    mma16(o[0][dj], pa[0], b0, b1);
                    mma16(o[1][dj], pa[1], b0, b1);
                }
            }
        }

        if (lane == 0) mbar_arrive(mempt + cur * 8);   // warp done with buffer
    }

    // --- normalize + store fp16 ---
    #pragma unroll
    for (int i = 0; i < 2; i++) {
        float inv0 = 1.f / lf[i][0], inv1 = 1.f / lf[i][2];
        int row0 = q0 + rb + i * 16 + g;
        __half* op0 = att_out + ((size_t)(bT + row0)) * DM + hh * 64;
        __half* op1 = op0 + (size_t)8 * DM;
        #pragma unroll
        for (int dj = 0; dj < 8; dj++) {
            int col = dj * 8 + 2 * tig;
            *(__half2*)(op0 + col) = __floats2half2_rn(o[i][dj][0] * inv0,
                                                       o[i][dj][1] * inv0);
            *(__half2*)(op1 + col) = __floats2half2_rn(o[i][dj][2] * inv1,
                                                       o[i][dj][3] * inv1);
        }
    }
}

// ---------------------------------------------------------------------------
// Host: tensor map construction (driver entry point via cudart; no -lcuda)
// ---------------------------------------------------------------------------
typedef CUresult (*PFN_tmEncode)(
    CUtensorMap*, CUtensorMapDataType, cuuint32_t, void*,
    const cuuint64_t*, const cuuint64_t*, const cuuint32_t*, const cuuint32_t*,
    CUtensorMapInterleave, CUtensorMapSwizzle, CUtensorMapL2promotion,
    CUtensorMapFloatOOBfill);

static void make_tm(CUtensorMap* tm, void* ptr, uint64_t d0, uint64_t d1,
                    uint32_t box0, uint32_t box1) {
    void* fn = nullptr;
    cudaDriverEntryPointQueryResult qr;
    cudaGetDriverEntryPoint("cuTensorMapEncodeTiled", &fn, cudaEnableDefault, &qr);
    cuuint64_t dims[2]    = {d0, d1};
    cuuint64_t strides[1] = {d0 * 2};
    cuuint32_t box[2]     = {box0, box1};
    cuuint32_t es[2]      = {1, 1};
    ((PFN_tmEncode)fn)(tm, CU_TENSOR_MAP_DATA_TYPE_FLOAT16, 2, ptr,
                       dims, strides, box, es,
                       CU_TENSOR_MAP_INTERLEAVE_NONE, CU_TENSOR_MAP_SWIZZLE_128B,
                       CU_TENSOR_MAP_L2_PROMOTION_L2_128B,
                       CU_TENSOR_MAP_FLOAT_OOB_FILL_NONE);
}

// ---------------------------------------------------------------------------
// kernel_launch
// Inputs: 0:x  1:mask(unused)  2:freqs_cos  3:freqs_sin
//         4:qkv_w  5:qkv_b  6:proj_w  7:proj_b
// ---------------------------------------------------------------------------
extern "C" void kernel_launch(void* const* d_in, const int* in_sizes, int n_in,
                              void* d_out, int out_size) {
    const float* x      = (const float*)d_in[0];
    const float* fcos   = (const float*)d_in[2];
    const float* fsin   = (const float*)d_in[3];
    const float* qkv_w  = (const float*)d_in[4];
    const float* qkv_b  = (const float*)d_in[5];
    const float* proj_w = (const float*)d_in[6];
    const float* proj_b = (const float*)d_in[7];
    float* out = (float*)d_out;

    __half *qkv2, *att, *x16, *wq, *wp;
    cudaGetSymbolAddress((void**)&qkv2, g_qkv2);
    cudaGetSymbolAddress((void**)&att,  g_att);
    cudaGetSymbolAddress((void**)&x16,  g_x16);
    cudaGetSymbolAddress((void**)&wq,   g_wq);
    cudaGetSymbolAddress((void**)&wp,   g_wp);

    cudaFuncSetAttribute(gemm_tc, cudaFuncAttributeMaxDynamicSharedMemorySize,
                         GSMEM_TOTAL);
    cudaFuncSetAttribute(attn_tc, cudaFuncAttributeMaxDynamicSharedMemorySize,
                         ASMEM_TOTAL);

    const int M = BB * TT;   // 8192

    CUtensorMap tmX, tmWq, tmAtt, tmWp, tmQ, tmKV;
    make_tm(&tmX,   x16,  DM,     M,      64, 128);
    make_tm(&tmWq,  wq,   DM,     3 * DM, 64, 128);
    make_tm(&tmAtt, att,  DM,     M,      64, 128);
    make_tm(&tmWp,  wp,   DM,     DM,     64, 128);
    make_tm(&tmQ,   qkv2, 3 * DM, M,      64, 128);
    make_tm(&tmKV,  qkv2, 3 * DM, M,      64, 64);

    // 0) operand prep: fp32 -> fp16
    prep_plain<<<(M * DM / 8) / 256, 256>>>(x, x16, M * DM / 8);
    prep_plain<<<(3 * DM * DM / 8) / 256, 256>>>(qkv_w, wq, 3 * DM * DM / 8);
    prep_plain<<<(DM * DM / 8) / 256, 256>>>(proj_w, wp, DM * DM / 8);

    // 1) QKV GEMM (TMA) with fused rope epilogue -> qkv2 (fp16)
    {
        dim3 grid(3 * DM / 128, M / 128);
        gemm_tc<<<grid, 256, GSMEM_TOTAL>>>(tmX, tmWq, qkv_b, qkv2, M, 3 * DM, DM,
                                            1, fcos, fsin);
    }
    // 2) causal attention (TMA, mbarrier ring) -> att (fp16)
    {
        dim3 grid(TT / 128, BB * NH);
        attn_tc<<<grid, 128, ASMEM_TOTAL>>>(tmQ, tmKV, att);
    }
    // 3) output projection (TMA) -> d_out (fp32)
    {
        dim3 grid(DM / 128, M / 128);
        gemm_tc<<<grid, 256, GSMEM_TOTAL>>>(tmAtt, tmWp, proj_b, out, M, DM, DM,
                                            0, nullptr, nullptr);
    }
}